// round 14
// baseline (speedup 1.0000x reference)
#include <cuda_runtime.h>
#include <cuda_fp16.h>
#include <math.h>
#include <stdint.h>

// Problem dims (fixed)
#define BB   8
#define NN   4096
#define CC   256
#define HH   8
#define DH   32
#define HW   64
#define NK   256
#define HID  1024
#define KPATCH 4096   // C * SR * SR

// ---------------- scratch (device globals; no allocation) ----------------
__device__ __half g_h_h [(size_t)BB*NN*CC];
__device__ __half g_wtT [(size_t)CC*KPATCH];
__device__ __half g_hs_h[(size_t)BB*NK*CC];
__device__ __half g_q_h [(size_t)BB*NN*CC];
__device__ __half g_kv_h[(size_t)BB*NK*2*CC];
__device__ __half g_o_h [(size_t)BB*NN*CC];
__device__ float  g_x1  [(size_t)BB*NN*CC];
__device__ __half g_h2_h[(size_t)BB*NN*CC];
__device__ __half g_m_h [(size_t)BB*NN*HID];
__device__ __half g_mi_h[(size_t)BB*NN*HID];
__device__ float  g_part[(size_t)8*BB*NK*CC];   // split-K partials
// transposed weights [N x K] fp16
__device__ __half g_qT [CC*CC];
__device__ __half g_kvT[2*CC*CC];
__device__ __half g_pjT[CC*CC];
__device__ __half g_f1T[HID*CC];
__device__ __half g_f2T[CC*HID];

// ---------------- PTX helpers (legal on base compute_103 target) ----------------
__device__ __forceinline__ uint32_t smem_u32(const void* p) {
    uint32_t a;
    asm("{ .reg .u64 t; cvta.to.shared.u64 t, %1; cvt.u32.u64 %0, t; }" : "=r"(a) : "l"(p));
    return a;
}
__device__ __forceinline__ void cpasync16(uint32_t dst, const void* src) {
    asm volatile("cp.async.cg.shared.global [%0], [%1], 16;" :: "r"(dst), "l"(src) : "memory");
}
__device__ __forceinline__ void cpcommit() {
    asm volatile("cp.async.commit_group;" ::: "memory");
}
template<int Ngrp> __device__ __forceinline__ void cpwait() {
    asm volatile("cp.async.wait_group %0;" :: "n"(Ngrp) : "memory");
}
__device__ __forceinline__ void ldm4(uint32_t* r, uint32_t addr) {
    asm volatile("ldmatrix.sync.aligned.m8n8.x4.shared.b16 {%0,%1,%2,%3}, [%4];"
                 : "=r"(r[0]), "=r"(r[1]), "=r"(r[2]), "=r"(r[3]) : "r"(addr));
}
__device__ __forceinline__ void mma16816h(float* c, const uint32_t* a, const uint32_t* b) {
    asm volatile("mma.sync.aligned.m16n8k16.row.col.f32.f16.f16.f32 "
                 "{%0,%1,%2,%3}, {%4,%5,%6,%7}, {%8,%9}, {%0,%1,%2,%3};"
                 : "+f"(c[0]), "+f"(c[1]), "+f"(c[2]), "+f"(c[3])
                 : "r"(a[0]), "r"(a[1]), "r"(a[2]), "r"(a[3]), "r"(b[0]), "r"(b[1]));
}
__device__ __forceinline__ uint32_t packh2(float x, float y) {
    __half2 h = __floats2half2_rn(x, y);
    return *reinterpret_cast<uint32_t*>(&h);
}

// ---------------- fp16 tensor GEMM via mma.sync, 3-stage pipeline ----------------
#define GEMM_SMEM (3 * 20480)

__global__ __launch_bounds__(256, 2)
void gemm_h(const __half* __restrict__ A, const __half* __restrict__ Bt,
            const float* __restrict__ bias, const float* __restrict__ res,
            float* __restrict__ Cf, __half* __restrict__ Ch,
            int M, int N, int K, int splitK)
{
    extern __shared__ char sm[];
    uint32_t sb = smem_u32(sm);
    const int tid  = threadIdx.x;
    const int warp = tid >> 5, lane = tid & 31;
    const int n0 = blockIdx.x * 128, m0 = blockIdx.y * 128;
    const int Keff  = K / splitK;
    const int kbase = blockIdx.z * Keff;
    if (splitK > 1) Cf += (size_t)blockIdx.z * M * N;
    const int nk = Keff / 32;
    const int wm0 = (warp >> 2) * 64, wn0 = (warp & 3) * 32;

    float c[4][4][4];
#pragma unroll
    for (int i = 0; i < 4; i++)
#pragma unroll
        for (int j = 0; j < 4; j++)
#pragma unroll
            for (int k = 0; k < 4; k++) c[i][j][k] = 0.f;

    const int lrow = tid >> 2;
    const int lq   = tid & 3;

    auto load_stage = [&](int i, int s) {
        const int k0 = kbase + i * 32;
        const uint32_t st = sb + s * 20480;
#pragma unroll
        for (int e = 0; e < 2; e++) {
            int r = lrow + e * 64;
            cpasync16(st +         r * 80 + lq * 16, A  + (size_t)(m0 + r) * K + k0 + lq * 8);
            cpasync16(st + 10240 + r * 80 + lq * 16, Bt + (size_t)(n0 + r) * K + k0 + lq * 8);
        }
        cpcommit();
    };

    auto compute_stage = [&](int s) {
        const uint32_t st = sb + s * 20480;
#pragma unroll
        for (int h = 0; h < 2; h++) {
            uint32_t a[4][4], bfr[4][2];
#pragma unroll
            for (int mt = 0; mt < 4; mt++) {
                int r = wm0 + mt * 16 + (lane & 15);
                ldm4(a[mt], st + r * 80 + h * 32 + (lane >> 4) * 16);
            }
#pragma unroll
            for (int ng = 0; ng < 2; ng++) {
                int r = wn0 + ng * 16 + (lane & 15);
                uint32_t t[4];
                ldm4(t, st + 10240 + r * 80 + h * 32 + (lane >> 4) * 16);
                bfr[2*ng][0] = t[0]; bfr[2*ng][1] = t[2];
                bfr[2*ng+1][0] = t[1]; bfr[2*ng+1][1] = t[3];
            }
#pragma unroll
            for (int mt = 0; mt < 4; mt++)
#pragma unroll
                for (int nt = 0; nt < 4; nt++)
                    mma16816h(c[mt][nt], a[mt], bfr[nt]);
        }
    };

    load_stage(0, 0);
    load_stage(1, 1);
    int stage = 0;
    for (int i = 0; i < nk; i++) {
        cpwait<1>();
        __syncthreads();
        if (i + 2 < nk) {
            int s2 = stage + 2; if (s2 >= 3) s2 -= 3;
            load_stage(i + 2, s2);
        }
        compute_stage(stage);
        if (++stage == 3) stage = 0;
    }

#pragma unroll
    for (int mt = 0; mt < 4; mt++)
#pragma unroll
        for (int nt = 0; nt < 4; nt++) {
            int row = m0 + wm0 + mt * 16 + (lane >> 2);
            int col = n0 + wn0 + nt * 8 + (lane & 3) * 2;
            float v0 = c[mt][nt][0], v1 = c[mt][nt][1];
            float v2 = c[mt][nt][2], v3 = c[mt][nt][3];
            if (splitK == 1) {
                float b0 = bias[col], b1 = bias[col + 1];
                v0 += b0; v1 += b1; v2 += b0; v3 += b1;
                if (res) {
                    const float* r0 = res + (size_t)row * N + col;
                    const float* r1 = res + (size_t)(row + 8) * N + col;
                    v0 += r0[0]; v1 += r0[1]; v2 += r1[0]; v3 += r1[1];
                }
            }
            if (Ch) {
                *reinterpret_cast<__half2*>(Ch + (size_t)row * N + col)       = __floats2half2_rn(v0, v1);
                *reinterpret_cast<__half2*>(Ch + (size_t)(row + 8) * N + col) = __floats2half2_rn(v2, v3);
            } else {
                *reinterpret_cast<float2*>(Cf + (size_t)row * N + col)       = make_float2(v0, v1);
                *reinterpret_cast<float2*>(Cf + (size_t)(row + 8) * N + col) = make_float2(v2, v3);
            }
        }
}

// ---------------- SR GEMM with IMPLICIT patch gather ----------------
__global__ __launch_bounds__(256, 2)
void gemm_sr(const __half* __restrict__ Ah, const __half* __restrict__ Bt,
             float* __restrict__ Cf, int M, int N, int K, int splitK)
{
    extern __shared__ char sm[];
    uint32_t sb = smem_u32(sm);
    const int tid  = threadIdx.x;
    const int warp = tid >> 5, lane = tid & 31;
    const int n0 = blockIdx.x * 128, m0 = blockIdx.y * 128;
    const int Keff  = K / splitK;
    const int kbase = blockIdx.z * Keff;
    Cf += (size_t)blockIdx.z * M * N;
    const int nk = Keff / 32;
    const int wm0 = (warp >> 2) * 64, wn0 = (warp & 3) * 32;

    float c[4][4][4];
#pragma unroll
    for (int i = 0; i < 4; i++)
#pragma unroll
        for (int j = 0; j < 4; j++)
#pragma unroll
            for (int k = 0; k < 4; k++) c[i][j][k] = 0.f;

    const int lrow = tid >> 2;
    const int lq   = tid & 3;

    auto load_stage = [&](int i, int s) {
        const int k0 = kbase + i * 32;
        const int ks = k0 >> 8;
        const int kc = (k0 & 255) + lq * 8;
        const int ky = ks >> 2, kx = ks & 3;
        const uint32_t st = sb + s * 20480;
#pragma unroll
        for (int e = 0; e < 2; e++) {
            int r = lrow + e * 64;
            int row = m0 + r;
            int bb = row >> 8, nkr = row & 255;
            int n = ((nkr >> 4) * 4 + ky) * HW + (nkr & 15) * 4 + kx;
            cpasync16(st +         r * 80 + lq * 16, Ah + ((size_t)bb * NN + n) * 256 + kc);
            cpasync16(st + 10240 + r * 80 + lq * 16, Bt + (size_t)(n0 + r) * K + k0 + lq * 8);
        }
        cpcommit();
    };

    auto compute_stage = [&](int s) {
        const uint32_t st = sb + s * 20480;
#pragma unroll
        for (int h = 0; h < 2; h++) {
            uint32_t a[4][4], bfr[4][2];
#pragma unroll
            for (int mt = 0; mt < 4; mt++) {
                int r = wm0 + mt * 16 + (lane & 15);
                ldm4(a[mt], st + r * 80 + h * 32 + (lane >> 4) * 16);
            }
#pragma unroll
            for (int ng = 0; ng < 2; ng++) {
                int r = wn0 + ng * 16 + (lane & 15);
                uint32_t t[4];
                ldm4(t, st + 10240 + r * 80 + h * 32 + (lane >> 4) * 16);
                bfr[2*ng][0] = t[0]; bfr[2*ng][1] = t[2];
                bfr[2*ng+1][0] = t[1]; bfr[2*ng+1][1] = t[3];
            }
#pragma unroll
            for (int mt = 0; mt < 4; mt++)
#pragma unroll
                for (int nt = 0; nt < 4; nt++)
                    mma16816h(c[mt][nt], a[mt], bfr[nt]);
        }
    };

    load_stage(0, 0);
    load_stage(1, 1);
    int stage = 0;
    for (int i = 0; i < nk; i++) {
        cpwait<1>();
        __syncthreads();
        if (i + 2 < nk) {
            int s2 = stage + 2; if (s2 >= 3) s2 -= 3;
            load_stage(i + 2, s2);
        }
        compute_stage(stage);
        if (++stage == 3) stage = 0;
    }

#pragma unroll
    for (int mt = 0; mt < 4; mt++)
#pragma unroll
        for (int nt = 0; nt < 4; nt++) {
            int row = m0 + wm0 + mt * 16 + (lane >> 2);
            int col = n0 + wn0 + nt * 8 + (lane & 3) * 2;
            *reinterpret_cast<float2*>(Cf + (size_t)row * N + col) =
                make_float2(c[mt][nt][0], c[mt][nt][1]);
            *reinterpret_cast<float2*>(Cf + (size_t)(row + 8) * N + col) =
                make_float2(c[mt][nt][2], c[mt][nt][3]);
        }
}

// ---------------- fused split-K reduce + bias + srn LayerNorm -> fp16 ----------------
__global__ void reduce_ln(const float* __restrict__ part, const float* __restrict__ cbias,
                          const float* __restrict__ w, const float* __restrict__ b,
                          __half* __restrict__ y, int MN, float eps)
{
    int row  = blockIdx.x * 8 + (threadIdx.x >> 5);
    int lane = threadIdx.x & 31;
    int c0 = lane * 8;
    float vals[8];
    {
        float4 b0 = *reinterpret_cast<const float4*>(cbias + c0);
        float4 b1 = *reinterpret_cast<const float4*>(cbias + c0 + 4);
        vals[0] = b0.x; vals[1] = b0.y; vals[2] = b0.z; vals[3] = b0.w;
        vals[4] = b1.x; vals[5] = b1.y; vals[6] = b1.z; vals[7] = b1.w;
    }
    for (int z = 0; z < 8; z++) {
        const float* p = part + (size_t)z * MN + (size_t)row * 256 + c0;
        float4 p0 = *reinterpret_cast<const float4*>(p);
        float4 p1 = *reinterpret_cast<const float4*>(p + 4);
        vals[0] += p0.x; vals[1] += p0.y; vals[2] += p0.z; vals[3] += p0.w;
        vals[4] += p1.x; vals[5] += p1.y; vals[6] += p1.z; vals[7] += p1.w;
    }
    float s = 0.f, sq = 0.f;
#pragma unroll
    for (int i = 0; i < 8; i++) { s += vals[i]; sq += vals[i] * vals[i]; }
#pragma unroll
    for (int o = 16; o > 0; o >>= 1) {
        s  += __shfl_xor_sync(0xffffffffu, s, o);
        sq += __shfl_xor_sync(0xffffffffu, sq, o);
    }
    float mean = s * (1.0f / 256.0f);
    float var  = sq * (1.0f / 256.0f) - mean * mean;
    float rs   = rsqrtf(var + eps);
    __align__(16) __half hb[8];
#pragma unroll
    for (int i = 0; i < 8; i++) {
        int c = c0 + i;
        hb[i] = __float2half_rn((vals[i] - mean) * rs * w[c] + b[c]);
    }
    *reinterpret_cast<uint4*>(y + (size_t)row * 256 + c0) = *reinterpret_cast<uint4*>(hb);
}

// ---------------- LayerNorm(256) -> fp16 ----------------
__global__ void ln256_h(const float* __restrict__ x, const float* __restrict__ w,
                        const float* __restrict__ b, __half* __restrict__ y,
                        int rows, float eps)
{
    int row  = blockIdx.x * 8 + (threadIdx.x >> 5);
    int lane = threadIdx.x & 31;
    if (row >= rows) return;
    const float* xr = x + (size_t)row * 256;
    float4 v0 = *reinterpret_cast<const float4*>(xr + lane * 8);
    float4 v1 = *reinterpret_cast<const float4*>(xr + lane * 8 + 4);
    float vals[8] = {v0.x, v0.y, v0.z, v0.w, v1.x, v1.y, v1.z, v1.w};
    float s = 0.f, sq = 0.f;
#pragma unroll
    for (int i = 0; i < 8; i++) { s += vals[i]; sq += vals[i] * vals[i]; }
#pragma unroll
    for (int o = 16; o > 0; o >>= 1) {
        s  += __shfl_xor_sync(0xffffffffu, s, o);
        sq += __shfl_xor_sync(0xffffffffu, sq, o);
    }
    float mean = s * (1.0f / 256.0f);
    float var  = sq * (1.0f / 256.0f) - mean * mean;
    float rs   = rsqrtf(var + eps);
    __align__(16) __half hb[8];
#pragma unroll
    for (int i = 0; i < 8; i++) {
        int c = lane * 8 + i;
        hb[i] = __float2half_rn((vals[i] - mean) * rs * w[c] + b[c]);
    }
    *reinterpret_cast<uint4*>(y + (size_t)row * 256 + lane * 8) = *reinterpret_cast<uint4*>(hb);
}

// ---------------- all weight prep in ONE kernel ----------------
#define PREP_TOTAL (65536 + 131072 + 65536 + 262144 + 262144 + 1048576)
__global__ void prep_all(const float* __restrict__ qw,  const float* __restrict__ kvw,
                         const float* __restrict__ pjw, const float* __restrict__ f1w,
                         const float* __restrict__ f2w, const float* __restrict__ srw,
                         __half* __restrict__ qT,  __half* __restrict__ kvT,
                         __half* __restrict__ pjT, __half* __restrict__ f1T,
                         __half* __restrict__ f2T, __half* __restrict__ wtT)
{
    int idx = blockIdx.x * 256 + threadIdx.x;
    if (idx < 65536) {
        int n = idx >> 8, k = idx & 255;
        qT[idx] = __float2half_rn(qw[k * 256 + n]);
        return;
    }
    idx -= 65536;
    if (idx < 131072) {
        int n = idx >> 8, k = idx & 255;
        kvT[idx] = __float2half_rn(kvw[k * 512 + n]);
        return;
    }
    idx -= 131072;
    if (idx < 65536) {
        int n = idx >> 8, k = idx & 255;
        pjT[idx] = __float2half_rn(pjw[k * 256 + n]);
        return;
    }
    idx -= 65536;
    if (idx < 262144) {
        int n = idx >> 8, k = idx & 255;
        f1T[idx] = __float2half_rn(f1w[k * 1024 + n]);
        return;
    }
    idx -= 262144;
    if (idx < 262144) {
        int n = idx >> 10, k = idx & 1023;
        f2T[idx] = __float2half_rn(f2w[k * 256 + n]);
        return;
    }
    idx -= 262144;
    {
        int co = idx >> 12, k = idx & 4095;
        int ks = k >> 8, ci = k & 255;
        wtT[idx] = __float2half_rn(srw[(size_t)co * KPATCH + ci * 16 + ks]);
    }
}

// ---------------- tensor-core attention, 64 q-row tiles, 2 CTAs/SM ----------------
// pos_2D is prefetched via cp.async into smem at kernel entry (overlapped with QK+softmax).
// smem: KT 20480 | QT 5120 | VT 16896 | pmax/psum 2048 | pos 64x1040B = 66560 (Opart aliases pos)
#define AT_KT 0
#define AT_QT 20480
#define AT_VT 25600
#define AT_PM 42496
#define AT_PS 44544
#define POS_STRIDE 1040
#define ATTN_SMEM (44544 + 64 * POS_STRIDE)

__global__ __launch_bounds__(256, 2)
void attn_mma(const __half* __restrict__ qg, const __half* __restrict__ kvg,
              const float* __restrict__ pos, const float* __restrict__ alpha,
              __half* __restrict__ og)
{
    extern __shared__ char sm[];
    uint32_t sb = smem_u32(sm);
    const int tid = threadIdx.x, warp = tid >> 5, lane = tid & 31;
    const int n0 = blockIdx.x * 64, hh = blockIdx.y, b = blockIdx.z;

    // ---- prefetch pos tile (64 rows x 256 f32) via cp.async, commit once ----
    {
        const float* posb = pos + ((size_t)(b * HH + hh) * NN + n0) * NK;
        for (int t = tid; t < 4096; t += 256) {
            int r = t >> 6, ch = t & 63;
            cpasync16(sb + AT_PS + r * POS_STRIDE + ch * 16, posb + (size_t)r * NK + ch * 4);
        }
        cpcommit();
    }

    // ---- K/V/Q loads ----
    {
        const __half* kb = kvg + ((size_t)b * NK) * 512 + hh * 32;
        for (int t = tid; t < 1024; t += 256) {
            int m = t >> 2, ch = t & 3;
            uint4 v = *reinterpret_cast<const uint4*>(kb + (size_t)m * 512 + ch * 8);
            *reinterpret_cast<uint4*>(sm + AT_KT + m * 80 + ch * 16) = v;
        }
        const __half* vb = kb + 256;
        for (int t = tid; t < 1024; t += 256) {
            int m = t >> 2, ch = t & 3;
            union { uint4 u; __half h[8]; } v;
            v.u = *reinterpret_cast<const uint4*>(vb + (size_t)m * 512 + ch * 8);
#pragma unroll
            for (int j = 0; j < 8; j++)
                *reinterpret_cast<__half*>(sm + AT_VT + (ch * 8 + j) * 528 + m * 2) = v.h[j];
        }
        const __half* qb = qg + ((size_t)b * NN + n0) * 256 + hh * 32;
        for (int t = tid; t < 256; t += 256) {
            int r = t >> 2, ch = t & 3;
            uint4 v = *reinterpret_cast<const uint4*>(qb + (size_t)r * 256 + ch * 8);
            *reinterpret_cast<uint4*>(sm + AT_QT + r * 80 + ch * 16) = v;
        }
    }
    __syncthreads();

    const int wm = (warp >> 2) * 32, wn = (warp & 3) * 64, slab = warp & 3;

    // ---- phase 1: S = Q @ K^T ----
    float c[2][8][4];
#pragma unroll
    for (int i = 0; i < 2; i++)
#pragma unroll
        for (int j = 0; j < 8; j++)
#pragma unroll
            for (int k = 0; k < 4; k++) c[i][j][k] = 0.f;

#pragma unroll
    for (int h = 0; h < 2; h++) {
        uint32_t a[2][4], bf[8][2];
#pragma unroll
        for (int mt = 0; mt < 2; mt++) {
            int r = wm + mt * 16 + (lane & 15);
            ldm4(a[mt], sb + AT_QT + r * 80 + h * 32 + (lane >> 4) * 16);
        }
#pragma unroll
        for (int ng = 0; ng < 4; ng++) {
            int r = wn + ng * 16 + (lane & 15);
            uint32_t t[4];
            ldm4(t, sb + AT_KT + r * 80 + h * 32 + (lane >> 4) * 16);
            bf[2*ng][0] = t[0]; bf[2*ng][1] = t[2];
            bf[2*ng+1][0] = t[1]; bf[2*ng+1][1] = t[3];
        }
#pragma unroll
        for (int mt = 0; mt < 2; mt++)
#pragma unroll
            for (int nt = 0; nt < 8; nt++)
                mma16816h(c[mt][nt], a[mt], bf[nt]);
    }

    // ---- phase 2: softmax on fragments ----
    const float scale = 0.17677669529663687f;
    float a_ = alpha[0];
    float* pmax = reinterpret_cast<float*>(sm + AT_PM);   // 256 floats
    float* psum = pmax + 256;                             // 256 floats

#pragma unroll
    for (int mt = 0; mt < 2; mt++) {
        float m1 = -1e30f, m2 = -1e30f;
#pragma unroll
        for (int nt = 0; nt < 8; nt++) {
            m1 = fmaxf(m1, fmaxf(c[mt][nt][0], c[mt][nt][1]));
            m2 = fmaxf(m2, fmaxf(c[mt][nt][2], c[mt][nt][3]));
        }
        m1 = fmaxf(m1, __shfl_xor_sync(0xffffffffu, m1, 1));
        m1 = fmaxf(m1, __shfl_xor_sync(0xffffffffu, m1, 2));
        m2 = fmaxf(m2, __shfl_xor_sync(0xffffffffu, m2, 1));
        m2 = fmaxf(m2, __shfl_xor_sync(0xffffffffu, m2, 2));
        if ((lane & 3) == 0) {
            int r1 = wm + mt * 16 + (lane >> 2);
            pmax[r1 * 4 + slab] = m1;
            pmax[(r1 + 8) * 4 + slab] = m2;
        }
    }
    __syncthreads();

#pragma unroll
    for (int mt = 0; mt < 2; mt++) {
        int r1 = wm + mt * 16 + (lane >> 2);
        float g1 = fmaxf(fmaxf(pmax[r1*4], pmax[r1*4+1]), fmaxf(pmax[r1*4+2], pmax[r1*4+3]));
        int r2 = r1 + 8;
        float g2 = fmaxf(fmaxf(pmax[r2*4], pmax[r2*4+1]), fmaxf(pmax[r2*4+2], pmax[r2*4+3]));
        float s1 = 0.f, s2 = 0.f;
#pragma unroll
        for (int nt = 0; nt < 8; nt++) {
            c[mt][nt][0] = expf((c[mt][nt][0] - g1) * scale); s1 += c[mt][nt][0];
            c[mt][nt][1] = expf((c[mt][nt][1] - g1) * scale); s1 += c[mt][nt][1];
            c[mt][nt][2] = expf((c[mt][nt][2] - g2) * scale); s2 += c[mt][nt][2];
            c[mt][nt][3] = expf((c[mt][nt][3] - g2) * scale); s2 += c[mt][nt][3];
        }
        s1 += __shfl_xor_sync(0xffffffffu, s1, 1);
        s1 += __shfl_xor_sync(0xffffffffu, s1, 2);
        s2 += __shfl_xor_sync(0xffffffffu, s2, 1);
        s2 += __shfl_xor_sync(0xffffffffu, s2, 2);
        if ((lane & 3) == 0) {
            psum[r1 * 4 + slab] = s1;
            psum[r2 * 4 + slab] = s2;
        }
    }
    cpwait<0>();      // pos tile resident (each thread's own copies; barrier publishes)
    __syncthreads();

    // normalize + blend pos (from smem) + pack to A-fragments
    uint32_t af[2][4][4];
#pragma unroll
    for (int mt = 0; mt < 2; mt++) {
        int r1 = wm + mt * 16 + (lane >> 2);
        int r2 = r1 + 8;
        float s1 = psum[r1*4] + psum[r1*4+1] + psum[r1*4+2] + psum[r1*4+3];
        float s2 = psum[r2*4] + psum[r2*4+1] + psum[r2*4+2] + psum[r2*4+3];
        float i1 = (1.0f - a_) / s1, i2 = (1.0f - a_) / s2;
        const char* p1 = sm + AT_PS + r1 * POS_STRIDE + (wn + (lane & 3) * 2) * 4;
        const char* p2 = sm + AT_PS + r2 * POS_STRIDE + (wn + (lane & 3) * 2) * 4;
#pragma unroll
        for (int nt = 0; nt < 8; nt++) {
            float2 q1 = *reinterpret_cast<const float2*>(p1 + nt * 32);
            float2 q2 = *reinterpret_cast<const float2*>(p2 + nt * 32);
            c[mt][nt][0] = c[mt][nt][0] * i1 + a_ * q1.x;
            c[mt][nt][1] = c[mt][nt][1] * i1 + a_ * q1.y;
            c[mt][nt][2] = c[mt][nt][2] * i2 + a_ * q2.x;
            c[mt][nt][3] = c[mt][nt][3] * i2 + a_ * q2.y;
        }
#pragma unroll
        for (int j = 0; j < 4; j++) {
            af[mt][j][0] = packh2(c[mt][2*j][0],   c[mt][2*j][1]);
            af[mt][j][1] = packh2(c[mt][2*j][2],   c[mt][2*j][3]);
            af[mt][j][2] = packh2(c[mt][2*j+1][0], c[mt][2*j+1][1]);
            af[mt][j][3] = packh2(c[mt][2*j+1][2], c[mt][2*j+1][3]);
        }
    }
    __syncthreads();   // pos reads done; pos region reused as Opart below

    // ---- phase 3: O_partial = P_slab @ V_slab ----
    float oc[2][4][4];
#pragma unroll
    for (int i = 0; i < 2; i++)
#pragma unroll
        for (int j = 0; j < 4; j++)
#pragma unroll
            for (int k = 0; k < 4; k++) oc[i][j][k] = 0.f;

#pragma unroll
    for (int ks = 0; ks < 4; ks++) {
        uint32_t bv[4][2];
#pragma unroll
        for (int ng = 0; ng < 2; ng++) {
            int d = ng * 16 + (lane & 15);
            uint32_t t[4];
            ldm4(t, sb + AT_VT + d * 528 + (wn + ks * 16) * 2 + (lane >> 4) * 16);
            bv[2*ng][0] = t[0]; bv[2*ng][1] = t[2];
            bv[2*ng+1][0] = t[1]; bv[2*ng+1][1] = t[3];
        }
#pragma unroll
        for (int mt = 0; mt < 2; mt++)
#pragma unroll
            for (int nt = 0; nt < 4; nt++)
                mma16816h(oc[mt][nt], af[mt][ks], bv[nt]);
    }

    float* Op = reinterpret_cast<float*>(sm + AT_PS);   // aliases consumed pos tile
#pragma unroll
    for (int mt = 0; mt < 2; mt++)
#pragma unroll
        for (int nt = 0; nt < 4; nt++) {
            int r1 = wm + mt * 16 + (lane >> 2);
            int d  = nt * 8 + (lane & 3) * 2;
            *reinterpret_cast<float2*>(Op + ((r1 * 4 + slab) * 32 + d)) =
                make_float2(oc[mt][nt][0], oc[mt][nt][1]);
            *reinterpret_cast<float2*>(Op + (((r1 + 8) * 4 + slab) * 32 + d)) =
                make_float2(oc[mt][nt][2], oc[mt][nt][3]);
        }
    __syncthreads();

    for (int t = tid; t < 2048; t += 256) {
        int r = t >> 5, d = t & 31;
        float s = Op[(r*4+0)*32+d] + Op[(r*4+1)*32+d] + Op[(r*4+2)*32+d] + Op[(r*4+3)*32+d];
        og[((size_t)b * NN + n0 + r) * 256 + hh * 32 + d] = __float2half_rn(s);
    }
}

// ---------------- depthwise 3x3 + exact GELU (weights staged in smem) ----------------
__global__ void dw_gelu(const __half* __restrict__ m, const float* __restrict__ w,
                        const float* __restrict__ bias, __half* __restrict__ mi)
{
    __shared__ float wsm[HID * 9];
    __shared__ float bsm[HID];
    int y = blockIdx.x;
    int b = blockIdx.y;
    for (int i = threadIdx.x; i < HID * 9; i += blockDim.x) wsm[i] = w[i];
    for (int i = threadIdx.x; i < HID; i += blockDim.x) bsm[i] = bias[i];
    __syncthreads();

    for (int idx = threadIdx.x; idx < HW * (HID / 4); idx += blockDim.x) {
        int x  = idx >> 8;
        int c4 = idx & 255;
        int c  = c4 * 4;
        float acc[4] = {bsm[c], bsm[c+1], bsm[c+2], bsm[c+3]};
#pragma unroll
        for (int dy = -1; dy <= 1; dy++) {
            int yy = y + dy;
            if (yy < 0 || yy >= HW) continue;
#pragma unroll
            for (int dx = -1; dx <= 1; dx++) {
                int xx = x + dx;
                if (xx < 0 || xx >= HW) continue;
                int tap = (dy + 1) * 3 + (dx + 1);
                const __half2* p = reinterpret_cast<const __half2*>(
                    m + ((size_t)b * NN + yy * HW + xx) * HID + c);
                float2 f01 = __half22float2(p[0]);
                float2 f23 = __half22float2(p[1]);
                acc[0] += f01.x * wsm[(c + 0) * 9 + tap];
                acc[1] += f01.y * wsm[(c + 1) * 9 + tap];
                acc[2] += f23.x * wsm[(c + 2) * 9 + tap];
                acc[3] += f23.y * wsm[(c + 3) * 9 + tap];
            }
        }
        float gv[4];
#pragma unroll
        for (int j = 0; j < 4; j++)
            gv[j] = 0.5f * acc[j] * (1.0f + erff(acc[j] * 0.70710678118654752f));
        __half2* op = reinterpret_cast<__half2*>(mi + ((size_t)b * NN + y * HW + x) * HID + c);
        op[0] = __floats2half2_rn(gv[0], gv[1]);
        op[1] = __floats2half2_rn(gv[2], gv[3]);
    }
}

// ---------------- launch ----------------
extern "C" void kernel_launch(void* const* d_in, const int* in_sizes, int n_in,
                              void* d_out, int out_size)
{
    const float* x      = (const float*)d_in[0];
    const float* pos2d  = (const float*)d_in[1];
    const float* ln1_w  = (const float*)d_in[2];
    const float* ln1_b  = (const float*)d_in[3];
    const float* q_w    = (const float*)d_in[4];
    const float* q_b    = (const float*)d_in[5];
    const float* kv_w   = (const float*)d_in[6];
    const float* kv_b   = (const float*)d_in[7];
    const float* sr_w   = (const float*)d_in[8];
    const float* sr_b   = (const float*)d_in[9];
    const float* srn_w  = (const float*)d_in[10];
    const float* srn_b  = (const float*)d_in[11];
    const float* alpha  = (const float*)d_in[12];
    const float* proj_w = (const float*)d_in[13];
    const float* proj_b = (const float*)d_in[14];
    const float* ln2_w  = (const float*)d_in[15];
    const float* ln2_b  = (const float*)d_in[16];
    const float* fc1_w  = (const float*)d_in[17];
    const float* fc1_b  = (const float*)d_in[18];
    const float* dw_w   = (const float*)d_in[19];
    const float* dw_b   = (const float*)d_in[20];
    const float* fc2_w  = (const float*)d_in[21];
    const float* fc2_b  = (const float*)d_in[22];
    float* out = (float*)d_out;

    __half *h_h, *wtT, *hs_h, *q_h, *kv_h, *o_h, *h2_h, *m_h, *mi_h;
    __half *qT, *kvT, *pjT, *f1T, *f2T;
    float *x1, *part;
    cudaGetSymbolAddress((void**)&h_h,  g_h_h);
    cudaGetSymbolAddress((void**)&wtT,  g_wtT);
    cudaGetSymbolAddress((void**)&hs_h, g_hs_h);
    cudaGetSymbolAddress((void**)&q_h,  g_q_h);
    cudaGetSymbolAddress((void**)&kv_h, g_kv_h);
    cudaGetSymbolAddress((void**)&o_h,  g_o_h);
    cudaGetSymbolAddress((void**)&x1,   g_x1);
    cudaGetSymbolAddress((void**)&h2_h, g_h2_h);
    cudaGetSymbolAddress((void**)&m_h,  g_m_h);
    cudaGetSymbolAddress((void**)&mi_h, g_mi_h);
    cudaGetSymbolAddress((void**)&part, g_part);
    cudaGetSymbolAddress((void**)&qT,   g_qT);
    cudaGetSymbolAddress((void**)&kvT,  g_kvT);
    cudaGetSymbolAddress((void**)&pjT,  g_pjT);
    cudaGetSymbolAddress((void**)&f1T,  g_f1T);
    cudaGetSymbolAddress((void**)&f2T,  g_f2T);

    static bool cfg = false;
    if (!cfg) {
        cudaFuncSetAttribute(gemm_h,  cudaFuncAttributeMaxDynamicSharedMemorySize, GEMM_SMEM);
        cudaFuncSetAttribute(gemm_sr, cudaFuncAttributeMaxDynamicSharedMemorySize, GEMM_SMEM);
        cudaFuncSetAttribute(attn_mma, cudaFuncAttributeMaxDynamicSharedMemorySize, ATTN_SMEM);
        cfg = true;
    }

    const int ROWS = BB * NN;        // 32768
    const int ROWS_SR = BB * NK;     // 2048

    // 1. h = LN1(x) -> fp16
    ln256_h<<<ROWS / 8, 256>>>(x, ln1_w, ln1_b, h_h, ROWS, 1e-6f);
    // 2. all weight prep (one kernel)
    prep_all<<<PREP_TOTAL / 256, 256>>>(q_w, kv_w, proj_w, fc1_w, fc2_w, sr_w,
                                        qT, kvT, pjT, f1T, f2T, wtT);
    // 3. SR GEMM with implicit patch gather (split-K=8)
    gemm_sr<<<dim3(CC / 128, ROWS_SR / 128, 8), 256, GEMM_SMEM>>>(h_h, wtT, part,
                                                                  ROWS_SR, CC, KPATCH, 8);
    // 4. fused reduce + bias + srn LN -> fp16
    reduce_ln<<<ROWS_SR / 8, 256>>>(part, sr_b, srn_w, srn_b, hs_h, ROWS_SR * CC, 1e-5f);
    // 5. q = h @ q_w + q_b  (fp16 out)
    gemm_h<<<dim3(CC / 128, ROWS / 128), 256, GEMM_SMEM>>>(h_h, qT, q_b, nullptr,
                                                           nullptr, q_h, ROWS, CC, CC, 1);
    // 6. kv = hs @ kv_w + kv_b (fp16 out)
    gemm_h<<<dim3((2 * CC) / 128, ROWS_SR / 128), 256, GEMM_SMEM>>>(hs_h, kvT, kv_b, nullptr,
                                                                    nullptr, kv_h, ROWS_SR, 2 * CC, CC, 1);
    // 7. tensor-core attention (64-row tiles, pos prefetch) -> o fp16
    attn_mma<<<dim3(NN / 64, HH, BB), 256, ATTN_SMEM>>>(q_h, kv_h, pos2d, alpha, o_h);
    // 8. proj: x1 = x + o @ proj_w + proj_b
    gemm_h<<<dim3(CC / 128, ROWS / 128), 256, GEMM_SMEM>>>(o_h, pjT, proj_b, x,
                                                           x1, nullptr, ROWS, CC, CC, 1);
    // 9. h2 = LN2(x1) -> fp16
    ln256_h<<<ROWS / 8, 256>>>(x1, ln2_w, ln2_b, h2_h, ROWS, 1e-6f);
    // 10. fc1: m = h2 @ fc1_w + fc1_b (fp16 out)
    gemm_h<<<dim3(HID / 128, ROWS / 128), 256, GEMM_SMEM>>>(h2_h, f1T, fc1_b, nullptr,
                                                            nullptr, m_h, ROWS, HID, CC, 1);
    // 11. depthwise conv + gelu
    dw_gelu<<<dim3(HW, BB), 512>>>(m_h, dw_w, dw_b, mi_h);
    // 12. fc2: out = x1 + mi @ fc2_w + fc2_b
    gemm_h<<<dim3(CC / 128, ROWS / 128), 256, GEMM_SMEM>>>(mi_h, f2T, fc2_b, x1,
                                                           out, nullptr, ROWS, CC, HID, 1);
}

// round 15
// speedup vs baseline: 1.0408x; 1.0408x over previous
#include <cuda_runtime.h>
#include <cuda_fp16.h>
#include <math.h>
#include <stdint.h>

// Problem dims (fixed)
#define BB   8
#define NN   4096
#define CC   256
#define HH   8
#define DH   32
#define HW   64
#define NK   256
#define HID  1024
#define KPATCH 4096   // C * SR * SR

// ---------------- scratch (device globals; no allocation) ----------------
__device__ __half g_h_h [(size_t)BB*NN*CC];
__device__ __half g_wtT [(size_t)CC*KPATCH];
__device__ __half g_hs_h[(size_t)BB*NK*CC];
__device__ __half g_q_h [(size_t)BB*NN*CC];
__device__ __half g_kv_h[(size_t)BB*NK*2*CC];
__device__ __half g_o_h [(size_t)BB*NN*CC];
__device__ float  g_x1  [(size_t)BB*NN*CC];
__device__ __half g_h2_h[(size_t)BB*NN*CC];
__device__ __half g_m_h [(size_t)BB*NN*HID];
__device__ __half g_mi_h[(size_t)BB*NN*HID];
__device__ float  g_part[(size_t)8*BB*NK*CC];   // split-K partials
// transposed weights [N x K] fp16
__device__ __half g_qT [CC*CC];
__device__ __half g_kvT[2*CC*CC];
__device__ __half g_pjT[CC*CC];
__device__ __half g_f1T[HID*CC];
__device__ __half g_f2T[CC*HID];

// ---------------- PTX helpers (legal on base compute_103 target) ----------------
__device__ __forceinline__ uint32_t smem_u32(const void* p) {
    uint32_t a;
    asm("{ .reg .u64 t; cvta.to.shared.u64 t, %1; cvt.u32.u64 %0, t; }" : "=r"(a) : "l"(p));
    return a;
}
__device__ __forceinline__ void cpasync16(uint32_t dst, const void* src) {
    asm volatile("cp.async.cg.shared.global [%0], [%1], 16;" :: "r"(dst), "l"(src) : "memory");
}
__device__ __forceinline__ void cpcommit() {
    asm volatile("cp.async.commit_group;" ::: "memory");
}
template<int Ngrp> __device__ __forceinline__ void cpwait() {
    asm volatile("cp.async.wait_group %0;" :: "n"(Ngrp) : "memory");
}
__device__ __forceinline__ void ldm4(uint32_t* r, uint32_t addr) {
    asm volatile("ldmatrix.sync.aligned.m8n8.x4.shared.b16 {%0,%1,%2,%3}, [%4];"
                 : "=r"(r[0]), "=r"(r[1]), "=r"(r[2]), "=r"(r[3]) : "r"(addr));
}
__device__ __forceinline__ void mma16816h(float* c, const uint32_t* a, const uint32_t* b) {
    asm volatile("mma.sync.aligned.m16n8k16.row.col.f32.f16.f16.f32 "
                 "{%0,%1,%2,%3}, {%4,%5,%6,%7}, {%8,%9}, {%0,%1,%2,%3};"
                 : "+f"(c[0]), "+f"(c[1]), "+f"(c[2]), "+f"(c[3])
                 : "r"(a[0]), "r"(a[1]), "r"(a[2]), "r"(a[3]), "r"(b[0]), "r"(b[1]));
}
__device__ __forceinline__ uint32_t packh2(float x, float y) {
    __half2 h = __floats2half2_rn(x, y);
    return *reinterpret_cast<uint32_t*>(&h);
}

// ---------------- fp16 tensor GEMM via mma.sync, 3-stage pipeline ----------------
#define GEMM_SMEM (3 * 20480)

__global__ __launch_bounds__(256, 2)
void gemm_h(const __half* __restrict__ A, const __half* __restrict__ Bt,
            const float* __restrict__ bias, const float* __restrict__ res,
            float* __restrict__ Cf, __half* __restrict__ Ch,
            int M, int N, int K, int splitK)
{
    extern __shared__ char sm[];
    uint32_t sb = smem_u32(sm);
    const int tid  = threadIdx.x;
    const int warp = tid >> 5, lane = tid & 31;
    const int n0 = blockIdx.x * 128, m0 = blockIdx.y * 128;
    const int Keff  = K / splitK;
    const int kbase = blockIdx.z * Keff;
    if (splitK > 1) Cf += (size_t)blockIdx.z * M * N;
    const int nk = Keff / 32;
    const int wm0 = (warp >> 2) * 64, wn0 = (warp & 3) * 32;

    float c[4][4][4];
#pragma unroll
    for (int i = 0; i < 4; i++)
#pragma unroll
        for (int j = 0; j < 4; j++)
#pragma unroll
            for (int k = 0; k < 4; k++) c[i][j][k] = 0.f;

    const int lrow = tid >> 2;
    const int lq   = tid & 3;

    auto load_stage = [&](int i, int s) {
        const int k0 = kbase + i * 32;
        const uint32_t st = sb + s * 20480;
#pragma unroll
        for (int e = 0; e < 2; e++) {
            int r = lrow + e * 64;
            cpasync16(st +         r * 80 + lq * 16, A  + (size_t)(m0 + r) * K + k0 + lq * 8);
            cpasync16(st + 10240 + r * 80 + lq * 16, Bt + (size_t)(n0 + r) * K + k0 + lq * 8);
        }
        cpcommit();
    };

    auto compute_stage = [&](int s) {
        const uint32_t st = sb + s * 20480;
#pragma unroll
        for (int h = 0; h < 2; h++) {
            uint32_t a[4][4], bfr[4][2];
#pragma unroll
            for (int mt = 0; mt < 4; mt++) {
                int r = wm0 + mt * 16 + (lane & 15);
                ldm4(a[mt], st + r * 80 + h * 32 + (lane >> 4) * 16);
            }
#pragma unroll
            for (int ng = 0; ng < 2; ng++) {
                int r = wn0 + ng * 16 + (lane & 15);
                uint32_t t[4];
                ldm4(t, st + 10240 + r * 80 + h * 32 + (lane >> 4) * 16);
                bfr[2*ng][0] = t[0]; bfr[2*ng][1] = t[2];
                bfr[2*ng+1][0] = t[1]; bfr[2*ng+1][1] = t[3];
            }
#pragma unroll
            for (int mt = 0; mt < 4; mt++)
#pragma unroll
                for (int nt = 0; nt < 4; nt++)
                    mma16816h(c[mt][nt], a[mt], bfr[nt]);
        }
    };

    load_stage(0, 0);
    load_stage(1, 1);
    int stage = 0;
    for (int i = 0; i < nk; i++) {
        cpwait<1>();
        __syncthreads();
        if (i + 2 < nk) {
            int s2 = stage + 2; if (s2 >= 3) s2 -= 3;
            load_stage(i + 2, s2);
        }
        compute_stage(stage);
        if (++stage == 3) stage = 0;
    }

#pragma unroll
    for (int mt = 0; mt < 4; mt++)
#pragma unroll
        for (int nt = 0; nt < 4; nt++) {
            int row = m0 + wm0 + mt * 16 + (lane >> 2);
            int col = n0 + wn0 + nt * 8 + (lane & 3) * 2;
            float v0 = c[mt][nt][0], v1 = c[mt][nt][1];
            float v2 = c[mt][nt][2], v3 = c[mt][nt][3];
            if (splitK == 1) {
                float b0 = bias[col], b1 = bias[col + 1];
                v0 += b0; v1 += b1; v2 += b0; v3 += b1;
                if (res) {
                    const float* r0 = res + (size_t)row * N + col;
                    const float* r1 = res + (size_t)(row + 8) * N + col;
                    v0 += r0[0]; v1 += r0[1]; v2 += r1[0]; v3 += r1[1];
                }
            }
            if (Ch) {
                *reinterpret_cast<__half2*>(Ch + (size_t)row * N + col)       = __floats2half2_rn(v0, v1);
                *reinterpret_cast<__half2*>(Ch + (size_t)(row + 8) * N + col) = __floats2half2_rn(v2, v3);
            } else {
                *reinterpret_cast<float2*>(Cf + (size_t)row * N + col)       = make_float2(v0, v1);
                *reinterpret_cast<float2*>(Cf + (size_t)(row + 8) * N + col) = make_float2(v2, v3);
            }
        }
}

// ---------------- SR GEMM with IMPLICIT patch gather ----------------
__global__ __launch_bounds__(256, 2)
void gemm_sr(const __half* __restrict__ Ah, const __half* __restrict__ Bt,
             float* __restrict__ Cf, int M, int N, int K, int splitK)
{
    extern __shared__ char sm[];
    uint32_t sb = smem_u32(sm);
    const int tid  = threadIdx.x;
    const int warp = tid >> 5, lane = tid & 31;
    const int n0 = blockIdx.x * 128, m0 = blockIdx.y * 128;
    const int Keff  = K / splitK;
    const int kbase = blockIdx.z * Keff;
    Cf += (size_t)blockIdx.z * M * N;
    const int nk = Keff / 32;
    const int wm0 = (warp >> 2) * 64, wn0 = (warp & 3) * 32;

    float c[4][4][4];
#pragma unroll
    for (int i = 0; i < 4; i++)
#pragma unroll
        for (int j = 0; j < 4; j++)
#pragma unroll
            for (int k = 0; k < 4; k++) c[i][j][k] = 0.f;

    const int lrow = tid >> 2;
    const int lq   = tid & 3;

    auto load_stage = [&](int i, int s) {
        const int k0 = kbase + i * 32;
        const int ks = k0 >> 8;
        const int kc = (k0 & 255) + lq * 8;
        const int ky = ks >> 2, kx = ks & 3;
        const uint32_t st = sb + s * 20480;
#pragma unroll
        for (int e = 0; e < 2; e++) {
            int r = lrow + e * 64;
            int row = m0 + r;
            int bb = row >> 8, nkr = row & 255;
            int n = ((nkr >> 4) * 4 + ky) * HW + (nkr & 15) * 4 + kx;
            cpasync16(st +         r * 80 + lq * 16, Ah + ((size_t)bb * NN + n) * 256 + kc);
            cpasync16(st + 10240 + r * 80 + lq * 16, Bt + (size_t)(n0 + r) * K + k0 + lq * 8);
        }
        cpcommit();
    };

    auto compute_stage = [&](int s) {
        const uint32_t st = sb + s * 20480;
#pragma unroll
        for (int h = 0; h < 2; h++) {
            uint32_t a[4][4], bfr[4][2];
#pragma unroll
            for (int mt = 0; mt < 4; mt++) {
                int r = wm0 + mt * 16 + (lane & 15);
                ldm4(a[mt], st + r * 80 + h * 32 + (lane >> 4) * 16);
            }
#pragma unroll
            for (int ng = 0; ng < 2; ng++) {
                int r = wn0 + ng * 16 + (lane & 15);
                uint32_t t[4];
                ldm4(t, st + 10240 + r * 80 + h * 32 + (lane >> 4) * 16);
                bfr[2*ng][0] = t[0]; bfr[2*ng][1] = t[2];
                bfr[2*ng+1][0] = t[1]; bfr[2*ng+1][1] = t[3];
            }
#pragma unroll
            for (int mt = 0; mt < 4; mt++)
#pragma unroll
                for (int nt = 0; nt < 4; nt++)
                    mma16816h(c[mt][nt], a[mt], bfr[nt]);
        }
    };

    load_stage(0, 0);
    load_stage(1, 1);
    int stage = 0;
    for (int i = 0; i < nk; i++) {
        cpwait<1>();
        __syncthreads();
        if (i + 2 < nk) {
            int s2 = stage + 2; if (s2 >= 3) s2 -= 3;
            load_stage(i + 2, s2);
        }
        compute_stage(stage);
        if (++stage == 3) stage = 0;
    }

#pragma unroll
    for (int mt = 0; mt < 4; mt++)
#pragma unroll
        for (int nt = 0; nt < 4; nt++) {
            int row = m0 + wm0 + mt * 16 + (lane >> 2);
            int col = n0 + wn0 + nt * 8 + (lane & 3) * 2;
            *reinterpret_cast<float2*>(Cf + (size_t)row * N + col) =
                make_float2(c[mt][nt][0], c[mt][nt][1]);
            *reinterpret_cast<float2*>(Cf + (size_t)(row + 8) * N + col) =
                make_float2(c[mt][nt][2], c[mt][nt][3]);
        }
}

// ---------------- fused split-K reduce + bias + srn LayerNorm -> fp16 ----------------
__global__ void reduce_ln(const float* __restrict__ part, const float* __restrict__ cbias,
                          const float* __restrict__ w, const float* __restrict__ b,
                          __half* __restrict__ y, int MN, float eps)
{
    int row  = blockIdx.x * 8 + (threadIdx.x >> 5);
    int lane = threadIdx.x & 31;
    int c0 = lane * 8;
    float vals[8];
    {
        float4 b0 = *reinterpret_cast<const float4*>(cbias + c0);
        float4 b1 = *reinterpret_cast<const float4*>(cbias + c0 + 4);
        vals[0] = b0.x; vals[1] = b0.y; vals[2] = b0.z; vals[3] = b0.w;
        vals[4] = b1.x; vals[5] = b1.y; vals[6] = b1.z; vals[7] = b1.w;
    }
    for (int z = 0; z < 8; z++) {
        const float* p = part + (size_t)z * MN + (size_t)row * 256 + c0;
        float4 p0 = *reinterpret_cast<const float4*>(p);
        float4 p1 = *reinterpret_cast<const float4*>(p + 4);
        vals[0] += p0.x; vals[1] += p0.y; vals[2] += p0.z; vals[3] += p0.w;
        vals[4] += p1.x; vals[5] += p1.y; vals[6] += p1.z; vals[7] += p1.w;
    }
    float s = 0.f, sq = 0.f;
#pragma unroll
    for (int i = 0; i < 8; i++) { s += vals[i]; sq += vals[i] * vals[i]; }
#pragma unroll
    for (int o = 16; o > 0; o >>= 1) {
        s  += __shfl_xor_sync(0xffffffffu, s, o);
        sq += __shfl_xor_sync(0xffffffffu, sq, o);
    }
    float mean = s * (1.0f / 256.0f);
    float var  = sq * (1.0f / 256.0f) - mean * mean;
    float rs   = rsqrtf(var + eps);
    __align__(16) __half hb[8];
#pragma unroll
    for (int i = 0; i < 8; i++) {
        int c = c0 + i;
        hb[i] = __float2half_rn((vals[i] - mean) * rs * w[c] + b[c]);
    }
    *reinterpret_cast<uint4*>(y + (size_t)row * 256 + c0) = *reinterpret_cast<uint4*>(hb);
}

// ---------------- LayerNorm(256) -> fp16 ----------------
__global__ void ln256_h(const float* __restrict__ x, const float* __restrict__ w,
                        const float* __restrict__ b, __half* __restrict__ y,
                        int rows, float eps)
{
    int row  = blockIdx.x * 8 + (threadIdx.x >> 5);
    int lane = threadIdx.x & 31;
    if (row >= rows) return;
    const float* xr = x + (size_t)row * 256;
    float4 v0 = *reinterpret_cast<const float4*>(xr + lane * 8);
    float4 v1 = *reinterpret_cast<const float4*>(xr + lane * 8 + 4);
    float vals[8] = {v0.x, v0.y, v0.z, v0.w, v1.x, v1.y, v1.z, v1.w};
    float s = 0.f, sq = 0.f;
#pragma unroll
    for (int i = 0; i < 8; i++) { s += vals[i]; sq += vals[i] * vals[i]; }
#pragma unroll
    for (int o = 16; o > 0; o >>= 1) {
        s  += __shfl_xor_sync(0xffffffffu, s, o);
        sq += __shfl_xor_sync(0xffffffffu, sq, o);
    }
    float mean = s * (1.0f / 256.0f);
    float var  = sq * (1.0f / 256.0f) - mean * mean;
    float rs   = rsqrtf(var + eps);
    __align__(16) __half hb[8];
#pragma unroll
    for (int i = 0; i < 8; i++) {
        int c = lane * 8 + i;
        hb[i] = __float2half_rn((vals[i] - mean) * rs * w[c] + b[c]);
    }
    *reinterpret_cast<uint4*>(y + (size_t)row * 256 + lane * 8) = *reinterpret_cast<uint4*>(hb);
}

// ---------------- all weight prep in ONE kernel ----------------
#define PREP_TOTAL (65536 + 131072 + 65536 + 262144 + 262144 + 1048576)
__global__ void prep_all(const float* __restrict__ qw,  const float* __restrict__ kvw,
                         const float* __restrict__ pjw, const float* __restrict__ f1w,
                         const float* __restrict__ f2w, const float* __restrict__ srw,
                         __half* __restrict__ qT,  __half* __restrict__ kvT,
                         __half* __restrict__ pjT, __half* __restrict__ f1T,
                         __half* __restrict__ f2T, __half* __restrict__ wtT)
{
    int idx = blockIdx.x * 256 + threadIdx.x;
    if (idx < 65536) {
        int n = idx >> 8, k = idx & 255;
        qT[idx] = __float2half_rn(qw[k * 256 + n]);
        return;
    }
    idx -= 65536;
    if (idx < 131072) {
        int n = idx >> 8, k = idx & 255;
        kvT[idx] = __float2half_rn(kvw[k * 512 + n]);
        return;
    }
    idx -= 131072;
    if (idx < 65536) {
        int n = idx >> 8, k = idx & 255;
        pjT[idx] = __float2half_rn(pjw[k * 256 + n]);
        return;
    }
    idx -= 65536;
    if (idx < 262144) {
        int n = idx >> 8, k = idx & 255;
        f1T[idx] = __float2half_rn(f1w[k * 1024 + n]);
        return;
    }
    idx -= 262144;
    if (idx < 262144) {
        int n = idx >> 10, k = idx & 1023;
        f2T[idx] = __float2half_rn(f2w[k * 256 + n]);
        return;
    }
    idx -= 262144;
    {
        int co = idx >> 12, k = idx & 4095;
        int ks = k >> 8, ci = k & 255;
        wtT[idx] = __float2half_rn(srw[(size_t)co * KPATCH + ci * 16 + ks]);
    }
}

// ---------------- tensor-core attention, 64 q-row tiles, 2 CTAs/SM ----------------
// pos_2D prefetched via cp.async AFTER the critical K/V/Q staging (overlaps QK+softmax).
// smem: KT 20480 | QT 5120 | VT 16896 | pmax/psum 2048 | pos 64x1040B = 66560 (Opart aliases pos)
#define AT_KT 0
#define AT_QT 20480
#define AT_VT 25600
#define AT_PM 42496
#define AT_PS 44544
#define POS_STRIDE 1040
#define ATTN_SMEM (44544 + 64 * POS_STRIDE)

__global__ __launch_bounds__(256, 2)
void attn_mma(const __half* __restrict__ qg, const __half* __restrict__ kvg,
              const float* __restrict__ pos, const float* __restrict__ alpha,
              __half* __restrict__ og)
{
    extern __shared__ char sm[];
    uint32_t sb = smem_u32(sm);
    const int tid = threadIdx.x, warp = tid >> 5, lane = tid & 31;
    const int n0 = blockIdx.x * 64, hh = blockIdx.y, b = blockIdx.z;

    // ---- K/V/Q loads FIRST (critical path for phase 1) ----
    {
        const __half* kb = kvg + ((size_t)b * NK) * 512 + hh * 32;
        for (int t = tid; t < 1024; t += 256) {
            int m = t >> 2, ch = t & 3;
            uint4 v = *reinterpret_cast<const uint4*>(kb + (size_t)m * 512 + ch * 8);
            *reinterpret_cast<uint4*>(sm + AT_KT + m * 80 + ch * 16) = v;
        }
        const __half* vb = kb + 256;
        for (int t = tid; t < 1024; t += 256) {
            int m = t >> 2, ch = t & 3;
            union { uint4 u; __half h[8]; } v;
            v.u = *reinterpret_cast<const uint4*>(vb + (size_t)m * 512 + ch * 8);
#pragma unroll
            for (int j = 0; j < 8; j++)
                *reinterpret_cast<__half*>(sm + AT_VT + (ch * 8 + j) * 528 + m * 2) = v.h[j];
        }
        const __half* qb = qg + ((size_t)b * NN + n0) * 256 + hh * 32;
        for (int t = tid; t < 256; t += 256) {
            int r = t >> 2, ch = t & 3;
            uint4 v = *reinterpret_cast<const uint4*>(qb + (size_t)r * 256 + ch * 8);
            *reinterpret_cast<uint4*>(sm + AT_QT + r * 80 + ch * 16) = v;
        }
    }

    // ---- pos tile prefetch (needed only at blend) — issued after critical loads ----
    {
        const float* posb = pos + ((size_t)(b * HH + hh) * NN + n0) * NK;
        for (int t = tid; t < 4096; t += 256) {
            int r = t >> 6, ch = t & 63;
            cpasync16(sb + AT_PS + r * POS_STRIDE + ch * 16, posb + (size_t)r * NK + ch * 4);
        }
        cpcommit();
    }
    __syncthreads();

    const int wm = (warp >> 2) * 32, wn = (warp & 3) * 64, slab = warp & 3;

    // ---- phase 1: S = Q @ K^T ----
    float c[2][8][4];
#pragma unroll
    for (int i = 0; i < 2; i++)
#pragma unroll
        for (int j = 0; j < 8; j++)
#pragma unroll
            for (int k = 0; k < 4; k++) c[i][j][k] = 0.f;

#pragma unroll
    for (int h = 0; h < 2; h++) {
        uint32_t a[2][4], bf[8][2];
#pragma unroll
        for (int mt = 0; mt < 2; mt++) {
            int r = wm + mt * 16 + (lane & 15);
            ldm4(a[mt], sb + AT_QT + r * 80 + h * 32 + (lane >> 4) * 16);
        }
#pragma unroll
        for (int ng = 0; ng < 4; ng++) {
            int r = wn + ng * 16 + (lane & 15);
            uint32_t t[4];
            ldm4(t, sb + AT_KT + r * 80 + h * 32 + (lane >> 4) * 16);
            bf[2*ng][0] = t[0]; bf[2*ng][1] = t[2];
            bf[2*ng+1][0] = t[1]; bf[2*ng+1][1] = t[3];
        }
#pragma unroll
        for (int mt = 0; mt < 2; mt++)
#pragma unroll
            for (int nt = 0; nt < 8; nt++)
                mma16816h(c[mt][nt], a[mt], bf[nt]);
    }

    // ---- phase 2: softmax on fragments ----
    const float scale = 0.17677669529663687f;
    float a_ = alpha[0];
    float* pmax = reinterpret_cast<float*>(sm + AT_PM);
    float* psum = pmax + 256;

#pragma unroll
    for (int mt = 0; mt < 2; mt++) {
        float m1 = -1e30f, m2 = -1e30f;
#pragma unroll
        for (int nt = 0; nt < 8; nt++) {
            m1 = fmaxf(m1, fmaxf(c[mt][nt][0], c[mt][nt][1]));
            m2 = fmaxf(m2, fmaxf(c[mt][nt][2], c[mt][nt][3]));
        }
        m1 = fmaxf(m1, __shfl_xor_sync(0xffffffffu, m1, 1));
        m1 = fmaxf(m1, __shfl_xor_sync(0xffffffffu, m1, 2));
        m2 = fmaxf(m2, __shfl_xor_sync(0xffffffffu, m2, 1));
        m2 = fmaxf(m2, __shfl_xor_sync(0xffffffffu, m2, 2));
        if ((lane & 3) == 0) {
            int r1 = wm + mt * 16 + (lane >> 2);
            pmax[r1 * 4 + slab] = m1;
            pmax[(r1 + 8) * 4 + slab] = m2;
        }
    }
    __syncthreads();

#pragma unroll
    for (int mt = 0; mt < 2; mt++) {
        int r1 = wm + mt * 16 + (lane >> 2);
        float g1 = fmaxf(fmaxf(pmax[r1*4], pmax[r1*4+1]), fmaxf(pmax[r1*4+2], pmax[r1*4+3]));
        int r2 = r1 + 8;
        float g2 = fmaxf(fmaxf(pmax[r2*4], pmax[r2*4+1]), fmaxf(pmax[r2*4+2], pmax[r2*4+3]));
        float s1 = 0.f, s2 = 0.f;
#pragma unroll
        for (int nt = 0; nt < 8; nt++) {
            c[mt][nt][0] = expf((c[mt][nt][0] - g1) * scale); s1 += c[mt][nt][0];
            c[mt][nt][1] = expf((c[mt][nt][1] - g1) * scale); s1 += c[mt][nt][1];
            c[mt][nt][2] = expf((c[mt][nt][2] - g2) * scale); s2 += c[mt][nt][2];
            c[mt][nt][3] = expf((c[mt][nt][3] - g2) * scale); s2 += c[mt][nt][3];
        }
        s1 += __shfl_xor_sync(0xffffffffu, s1, 1);
        s1 += __shfl_xor_sync(0xffffffffu, s1, 2);
        s2 += __shfl_xor_sync(0xffffffffu, s2, 1);
        s2 += __shfl_xor_sync(0xffffffffu, s2, 2);
        if ((lane & 3) == 0) {
            psum[r1 * 4 + slab] = s1;
            psum[r2 * 4 + slab] = s2;
        }
    }
    cpwait<0>();      // pos tile resident
    __syncthreads();

    // normalize + blend pos (from smem) + pack to A-fragments
    uint32_t af[2][4][4];
#pragma unroll
    for (int mt = 0; mt < 2; mt++) {
        int r1 = wm + mt * 16 + (lane >> 2);
        int r2 = r1 + 8;
        float s1 = psum[r1*4] + psum[r1*4+1] + psum[r1*4+2] + psum[r1*4+3];
        float s2 = psum[r2*4] + psum[r2*4+1] + psum[r2*4+2] + psum[r2*4+3];
        float i1 = (1.0f - a_) / s1, i2 = (1.0f - a_) / s2;
        const char* p1 = sm + AT_PS + r1 * POS_STRIDE + (wn + (lane & 3) * 2) * 4;
        const char* p2 = sm + AT_PS + r2 * POS_STRIDE + (wn + (lane & 3) * 2) * 4;
#pragma unroll
        for (int nt = 0; nt < 8; nt++) {
            float2 q1 = *reinterpret_cast<const float2*>(p1 + nt * 32);
            float2 q2 = *reinterpret_cast<const float2*>(p2 + nt * 32);
            c[mt][nt][0] = c[mt][nt][0] * i1 + a_ * q1.x;
            c[mt][nt][1] = c[mt][nt][1] * i1 + a_ * q1.y;
            c[mt][nt][2] = c[mt][nt][2] * i2 + a_ * q2.x;
            c[mt][nt][3] = c[mt][nt][3] * i2 + a_ * q2.y;
        }
#pragma unroll
        for (int j = 0; j < 4; j++) {
            af[mt][j][0] = packh2(c[mt][2*j][0],   c[mt][2*j][1]);
            af[mt][j][1] = packh2(c[mt][2*j][2],   c[mt][2*j][3]);
            af[mt][j][2] = packh2(c[mt][2*j+1][0], c[mt][2*j+1][1]);
            af[mt][j][3] = packh2(c[mt][2*j+1][2], c[mt][2*j+1][3]);
        }
    }
    __syncthreads();   // pos reads done; pos region reused as Opart

    // ---- phase 3: O_partial = P_slab @ V_slab ----
    float oc[2][4][4];
#pragma unroll
    for (int i = 0; i < 2; i++)
#pragma unroll
        for (int j = 0; j < 4; j++)
#pragma unroll
            for (int k = 0; k < 4; k++) oc[i][j][k] = 0.f;

#pragma unroll
    for (int ks = 0; ks < 4; ks++) {
        uint32_t bv[4][2];
#pragma unroll
        for (int ng = 0; ng < 2; ng++) {
            int d = ng * 16 + (lane & 15);
            uint32_t t[4];
            ldm4(t, sb + AT_VT + d * 528 + (wn + ks * 16) * 2 + (lane >> 4) * 16);
            bv[2*ng][0] = t[0]; bv[2*ng][1] = t[2];
            bv[2*ng+1][0] = t[1]; bv[2*ng+1][1] = t[3];
        }
#pragma unroll
        for (int mt = 0; mt < 2; mt++)
#pragma unroll
            for (int nt = 0; nt < 4; nt++)
                mma16816h(oc[mt][nt], af[mt][ks], bv[nt]);
    }

    float* Op = reinterpret_cast<float*>(sm + AT_PS);
#pragma unroll
    for (int mt = 0; mt < 2; mt++)
#pragma unroll
        for (int nt = 0; nt < 4; nt++) {
            int r1 = wm + mt * 16 + (lane >> 2);
            int d  = nt * 8 + (lane & 3) * 2;
            *reinterpret_cast<float2*>(Op + ((r1 * 4 + slab) * 32 + d)) =
                make_float2(oc[mt][nt][0], oc[mt][nt][1]);
            *reinterpret_cast<float2*>(Op + (((r1 + 8) * 4 + slab) * 32 + d)) =
                make_float2(oc[mt][nt][2], oc[mt][nt][3]);
        }
    __syncthreads();

    for (int t = tid; t < 2048; t += 256) {
        int r = t >> 5, d = t & 31;
        float s = Op[(r*4+0)*32+d] + Op[(r*4+1)*32+d] + Op[(r*4+2)*32+d] + Op[(r*4+3)*32+d];
        og[((size_t)b * NN + n0 + r) * 256 + hh * 32 + d] = __float2half_rn(s);
    }
}

// ---------------- depthwise 3x3 + exact GELU (weights staged in smem) ----------------
__global__ void dw_gelu(const __half* __restrict__ m, const float* __restrict__ w,
                        const float* __restrict__ bias, __half* __restrict__ mi)
{
    __shared__ float wsm[HID * 9];
    __shared__ float bsm[HID];
    int y = blockIdx.x;
    int b = blockIdx.y;
    for (int i = threadIdx.x; i < HID * 9; i += blockDim.x) wsm[i] = w[i];
    for (int i = threadIdx.x; i < HID; i += blockDim.x) bsm[i] = bias[i];
    __syncthreads();

    for (int idx = threadIdx.x; idx < HW * (HID / 4); idx += blockDim.x) {
        int x  = idx >> 8;
        int c4 = idx & 255;
        int c  = c4 * 4;
        float acc[4] = {bsm[c], bsm[c+1], bsm[c+2], bsm[c+3]};
#pragma unroll
        for (int dy = -1; dy <= 1; dy++) {
            int yy = y + dy;
            if (yy < 0 || yy >= HW) continue;
#pragma unroll
            for (int dx = -1; dx <= 1; dx++) {
                int xx = x + dx;
                if (xx < 0 || xx >= HW) continue;
                int tap = (dy + 1) * 3 + (dx + 1);
                const __half2* p = reinterpret_cast<const __half2*>(
                    m + ((size_t)b * NN + yy * HW + xx) * HID + c);
                float2 f01 = __half22float2(p[0]);
                float2 f23 = __half22float2(p[1]);
                acc[0] += f01.x * wsm[(c + 0) * 9 + tap];
                acc[1] += f01.y * wsm[(c + 1) * 9 + tap];
                acc[2] += f23.x * wsm[(c + 2) * 9 + tap];
                acc[3] += f23.y * wsm[(c + 3) * 9 + tap];
            }
        }
        float gv[4];
#pragma unroll
        for (int j = 0; j < 4; j++)
            gv[j] = 0.5f * acc[j] * (1.0f + erff(acc[j] * 0.70710678118654752f));
        __half2* op = reinterpret_cast<__half2*>(mi + ((size_t)b * NN + y * HW + x) * HID + c);
        op[0] = __floats2half2_rn(gv[0], gv[1]);
        op[1] = __floats2half2_rn(gv[2], gv[3]);
    }
}

// ---------------- launch ----------------
extern "C" void kernel_launch(void* const* d_in, const int* in_sizes, int n_in,
                              void* d_out, int out_size)
{
    const float* x      = (const float*)d_in[0];
    const float* pos2d  = (const float*)d_in[1];
    const float* ln1_w  = (const float*)d_in[2];
    const float* ln1_b  = (const float*)d_in[3];
    const float* q_w    = (const float*)d_in[4];
    const float* q_b    = (const float*)d_in[5];
    const float* kv_w   = (const float*)d_in[6];
    const float* kv_b   = (const float*)d_in[7];
    const float* sr_w   = (const float*)d_in[8];
    const float* sr_b   = (const float*)d_in[9];
    const float* srn_w  = (const float*)d_in[10];
    const float* srn_b  = (const float*)d_in[11];
    const float* alpha  = (const float*)d_in[12];
    const float* proj_w = (const float*)d_in[13];
    const float* proj_b = (const float*)d_in[14];
    const float* ln2_w  = (const float*)d_in[15];
    const float* ln2_b  = (const float*)d_in[16];
    const float* fc1_w  = (const float*)d_in[17];
    const float* fc1_b  = (const float*)d_in[18];
    const float* dw_w   = (const float*)d_in[19];
    const float* dw_b   = (const float*)d_in[20];
    const float* fc2_w  = (const float*)d_in[21];
    const float* fc2_b  = (const float*)d_in[22];
    float* out = (float*)d_out;

    __half *h_h, *wtT, *hs_h, *q_h, *kv_h, *o_h, *h2_h, *m_h, *mi_h;
    __half *qT, *kvT, *pjT, *f1T, *f2T;
    float *x1, *part;
    cudaGetSymbolAddress((void**)&h_h,  g_h_h);
    cudaGetSymbolAddress((void**)&wtT,  g_wtT);
    cudaGetSymbolAddress((void**)&hs_h, g_hs_h);
    cudaGetSymbolAddress((void**)&q_h,  g_q_h);
    cudaGetSymbolAddress((void**)&kv_h, g_kv_h);
    cudaGetSymbolAddress((void**)&o_h,  g_o_h);
    cudaGetSymbolAddress((void**)&x1,   g_x1);
    cudaGetSymbolAddress((void**)&h2_h, g_h2_h);
    cudaGetSymbolAddress((void**)&m_h,  g_m_h);
    cudaGetSymbolAddress((void**)&mi_h, g_mi_h);
    cudaGetSymbolAddress((void**)&part, g_part);
    cudaGetSymbolAddress((void**)&qT,   g_qT);
    cudaGetSymbolAddress((void**)&kvT,  g_kvT);
    cudaGetSymbolAddress((void**)&pjT,  g_pjT);
    cudaGetSymbolAddress((void**)&f1T,  g_f1T);
    cudaGetSymbolAddress((void**)&f2T,  g_f2T);

    static bool cfg = false;
    if (!cfg) {
        cudaFuncSetAttribute(gemm_h,  cudaFuncAttributeMaxDynamicSharedMemorySize, GEMM_SMEM);
        cudaFuncSetAttribute(gemm_sr, cudaFuncAttributeMaxDynamicSharedMemorySize, GEMM_SMEM);
        cudaFuncSetAttribute(attn_mma, cudaFuncAttributeMaxDynamicSharedMemorySize, ATTN_SMEM);
        cfg = true;
    }

    const int ROWS = BB * NN;        // 32768
    const int ROWS_SR = BB * NK;     // 2048

    // 1. h = LN1(x) -> fp16
    ln256_h<<<ROWS / 8, 256>>>(x, ln1_w, ln1_b, h_h, ROWS, 1e-6f);
    // 2. all weight prep (one kernel)
    prep_all<<<PREP_TOTAL / 256, 256>>>(q_w, kv_w, proj_w, fc1_w, fc2_w, sr_w,
                                        qT, kvT, pjT, f1T, f2T, wtT);
    // 3. SR GEMM with implicit patch gather (split-K=8)
    gemm_sr<<<dim3(CC / 128, ROWS_SR / 128, 8), 256, GEMM_SMEM>>>(h_h, wtT, part,
                                                                  ROWS_SR, CC, KPATCH, 8);
    // 4. fused reduce + bias + srn LN -> fp16
    reduce_ln<<<ROWS_SR / 8, 256>>>(part, sr_b, srn_w, srn_b, hs_h, ROWS_SR * CC, 1e-5f);
    // 5. q = h @ q_w + q_b  (fp16 out)
    gemm_h<<<dim3(CC / 128, ROWS / 128), 256, GEMM_SMEM>>>(h_h, qT, q_b, nullptr,
                                                           nullptr, q_h, ROWS, CC, CC, 1);
    // 6. kv = hs @ kv_w + kv_b (fp16 out)
    gemm_h<<<dim3((2 * CC) / 128, ROWS_SR / 128), 256, GEMM_SMEM>>>(hs_h, kvT, kv_b, nullptr,
                                                                    nullptr, kv_h, ROWS_SR, 2 * CC, CC, 1);
    // 7. tensor-core attention (64-row tiles, reordered pos prefetch) -> o fp16
    attn_mma<<<dim3(NN / 64, HH, BB), 256, ATTN_SMEM>>>(q_h, kv_h, pos2d, alpha, o_h);
    // 8. proj: x1 = x + o @ proj_w + proj_b
    gemm_h<<<dim3(CC / 128, ROWS / 128), 256, GEMM_SMEM>>>(o_h, pjT, proj_b, x,
                                                           x1, nullptr, ROWS, CC, CC, 1);
    // 9. h2 = LN2(x1) -> fp16
    ln256_h<<<ROWS / 8, 256>>>(x1, ln2_w, ln2_b, h2_h, ROWS, 1e-6f);
    // 10. fc1: m = h2 @ fc1_w + fc1_b (fp16 out)
    gemm_h<<<dim3(HID / 128, ROWS / 128), 256, GEMM_SMEM>>>(h2_h, f1T, fc1_b, nullptr,
                                                            nullptr, m_h, ROWS, HID, CC, 1);
    // 11. depthwise conv + gelu
    dw_gelu<<<dim3(HW, BB), 512>>>(m_h, dw_w, dw_b, mi_h);
    // 12. fc2: out = x1 + mi @ fc2_w + fc2_b
    gemm_h<<<dim3(CC / 128, ROWS / 128), 256, GEMM_SMEM>>>(mi_h, f2T, fc2_b, x1,
                                                           out, nullptr, ROWS, CC, HID, 1);
}

// round 16
// speedup vs baseline: 1.0554x; 1.0140x over previous
#include <cuda_runtime.h>
#include <cuda_fp16.h>
#include <math.h>
#include <stdint.h>

// Problem dims (fixed)
#define BB   8
#define NN   4096
#define CC   256
#define HH   8
#define DH   32
#define HW   64
#define NK   256
#define HID  1024
#define KPATCH 4096   // C * SR * SR

// ---------------- scratch (device globals; no allocation) ----------------
__device__ __half g_h_h [(size_t)BB*NN*CC];
__device__ __half g_wtT [(size_t)CC*KPATCH];
__device__ __half g_hs_h[(size_t)BB*NK*CC];
__device__ __half g_q_h [(size_t)BB*NN*CC];
__device__ __half g_kv_h[(size_t)BB*NK*2*CC];
__device__ __half g_o_h [(size_t)BB*NN*CC];
__device__ float  g_x1  [(size_t)BB*NN*CC];
__device__ __half g_h2_h[(size_t)BB*NN*CC];
__device__ __half g_m_h [(size_t)BB*NN*HID];
__device__ __half g_mi_h[(size_t)BB*NN*HID];
__device__ float  g_part[(size_t)8*BB*NK*CC];   // split-K partials
// transposed weights [N x K] fp16
__device__ __half g_qT [CC*CC];
__device__ __half g_kvT[2*CC*CC];
__device__ __half g_pjT[CC*CC];
__device__ __half g_f1T[HID*CC];
__device__ __half g_f2T[CC*HID];

// ---------------- PTX helpers (legal on base compute_103 target) ----------------
__device__ __forceinline__ uint32_t smem_u32(const void* p) {
    uint32_t a;
    asm("{ .reg .u64 t; cvta.to.shared.u64 t, %1; cvt.u32.u64 %0, t; }" : "=r"(a) : "l"(p));
    return a;
}
__device__ __forceinline__ void cpasync16(uint32_t dst, const void* src) {
    asm volatile("cp.async.cg.shared.global [%0], [%1], 16;" :: "r"(dst), "l"(src) : "memory");
}
__device__ __forceinline__ void cpcommit() {
    asm volatile("cp.async.commit_group;" ::: "memory");
}
template<int Ngrp> __device__ __forceinline__ void cpwait() {
    asm volatile("cp.async.wait_group %0;" :: "n"(Ngrp) : "memory");
}
__device__ __forceinline__ void ldm4(uint32_t* r, uint32_t addr) {
    asm volatile("ldmatrix.sync.aligned.m8n8.x4.shared.b16 {%0,%1,%2,%3}, [%4];"
                 : "=r"(r[0]), "=r"(r[1]), "=r"(r[2]), "=r"(r[3]) : "r"(addr));
}
__device__ __forceinline__ void mma16816h(float* c, const uint32_t* a, const uint32_t* b) {
    asm volatile("mma.sync.aligned.m16n8k16.row.col.f32.f16.f16.f32 "
                 "{%0,%1,%2,%3}, {%4,%5,%6,%7}, {%8,%9}, {%0,%1,%2,%3};"
                 : "+f"(c[0]), "+f"(c[1]), "+f"(c[2]), "+f"(c[3])
                 : "r"(a[0]), "r"(a[1]), "r"(a[2]), "r"(a[3]), "r"(b[0]), "r"(b[1]));
}
__device__ __forceinline__ uint32_t packh2(float x, float y) {
    __half2 h = __floats2half2_rn(x, y);
    return *reinterpret_cast<uint32_t*>(&h);
}

// ---------------- fp16 tensor GEMM via mma.sync, 3-stage pipeline ----------------
#define GEMM_SMEM (3 * 20480)

__global__ __launch_bounds__(256, 2)
void gemm_h(const __half* __restrict__ A, const __half* __restrict__ Bt,
            const float* __restrict__ bias, const float* __restrict__ res,
            float* __restrict__ Cf, __half* __restrict__ Ch,
            int M, int N, int K, int splitK)
{
    extern __shared__ char sm[];
    uint32_t sb = smem_u32(sm);
    const int tid  = threadIdx.x;
    const int warp = tid >> 5, lane = tid & 31;
    const int n0 = blockIdx.x * 128, m0 = blockIdx.y * 128;
    const int Keff  = K / splitK;
    const int kbase = blockIdx.z * Keff;
    if (splitK > 1) Cf += (size_t)blockIdx.z * M * N;
    const int nk = Keff / 32;
    const int wm0 = (warp >> 2) * 64, wn0 = (warp & 3) * 32;

    float c[4][4][4];
#pragma unroll
    for (int i = 0; i < 4; i++)
#pragma unroll
        for (int j = 0; j < 4; j++)
#pragma unroll
            for (int k = 0; k < 4; k++) c[i][j][k] = 0.f;

    const int lrow = tid >> 2;
    const int lq   = tid & 3;

    auto load_stage = [&](int i, int s) {
        const int k0 = kbase + i * 32;
        const uint32_t st = sb + s * 20480;
#pragma unroll
        for (int e = 0; e < 2; e++) {
            int r = lrow + e * 64;
            cpasync16(st +         r * 80 + lq * 16, A  + (size_t)(m0 + r) * K + k0 + lq * 8);
            cpasync16(st + 10240 + r * 80 + lq * 16, Bt + (size_t)(n0 + r) * K + k0 + lq * 8);
        }
        cpcommit();
    };

    auto compute_stage = [&](int s) {
        const uint32_t st = sb + s * 20480;
#pragma unroll
        for (int h = 0; h < 2; h++) {
            uint32_t a[4][4], bfr[4][2];
#pragma unroll
            for (int mt = 0; mt < 4; mt++) {
                int r = wm0 + mt * 16 + (lane & 15);
                ldm4(a[mt], st + r * 80 + h * 32 + (lane >> 4) * 16);
            }
#pragma unroll
            for (int ng = 0; ng < 2; ng++) {
                int r = wn0 + ng * 16 + (lane & 15);
                uint32_t t[4];
                ldm4(t, st + 10240 + r * 80 + h * 32 + (lane >> 4) * 16);
                bfr[2*ng][0] = t[0]; bfr[2*ng][1] = t[2];
                bfr[2*ng+1][0] = t[1]; bfr[2*ng+1][1] = t[3];
            }
#pragma unroll
            for (int mt = 0; mt < 4; mt++)
#pragma unroll
                for (int nt = 0; nt < 4; nt++)
                    mma16816h(c[mt][nt], a[mt], bfr[nt]);
        }
    };

    load_stage(0, 0);
    load_stage(1, 1);
    int stage = 0;
    for (int i = 0; i < nk; i++) {
        cpwait<1>();
        __syncthreads();
        if (i + 2 < nk) {
            int s2 = stage + 2; if (s2 >= 3) s2 -= 3;
            load_stage(i + 2, s2);
        }
        compute_stage(stage);
        if (++stage == 3) stage = 0;
    }

#pragma unroll
    for (int mt = 0; mt < 4; mt++)
#pragma unroll
        for (int nt = 0; nt < 4; nt++) {
            int row = m0 + wm0 + mt * 16 + (lane >> 2);
            int col = n0 + wn0 + nt * 8 + (lane & 3) * 2;
            float v0 = c[mt][nt][0], v1 = c[mt][nt][1];
            float v2 = c[mt][nt][2], v3 = c[mt][nt][3];
            if (splitK == 1) {
                float b0 = bias[col], b1 = bias[col + 1];
                v0 += b0; v1 += b1; v2 += b0; v3 += b1;
                if (res) {
                    const float* r0 = res + (size_t)row * N + col;
                    const float* r1 = res + (size_t)(row + 8) * N + col;
                    v0 += r0[0]; v1 += r0[1]; v2 += r1[0]; v3 += r1[1];
                }
            }
            if (Ch) {
                *reinterpret_cast<__half2*>(Ch + (size_t)row * N + col)       = __floats2half2_rn(v0, v1);
                *reinterpret_cast<__half2*>(Ch + (size_t)(row + 8) * N + col) = __floats2half2_rn(v2, v3);
            } else {
                *reinterpret_cast<float2*>(Cf + (size_t)row * N + col)       = make_float2(v0, v1);
                *reinterpret_cast<float2*>(Cf + (size_t)(row + 8) * N + col) = make_float2(v2, v3);
            }
        }
}

// ---------------- SR GEMM with IMPLICIT patch gather ----------------
__global__ __launch_bounds__(256, 2)
void gemm_sr(const __half* __restrict__ Ah, const __half* __restrict__ Bt,
             float* __restrict__ Cf, int M, int N, int K, int splitK)
{
    extern __shared__ char sm[];
    uint32_t sb = smem_u32(sm);
    const int tid  = threadIdx.x;
    const int warp = tid >> 5, lane = tid & 31;
    const int n0 = blockIdx.x * 128, m0 = blockIdx.y * 128;
    const int Keff  = K / splitK;
    const int kbase = blockIdx.z * Keff;
    Cf += (size_t)blockIdx.z * M * N;
    const int nk = Keff / 32;
    const int wm0 = (warp >> 2) * 64, wn0 = (warp & 3) * 32;

    float c[4][4][4];
#pragma unroll
    for (int i = 0; i < 4; i++)
#pragma unroll
        for (int j = 0; j < 4; j++)
#pragma unroll
            for (int k = 0; k < 4; k++) c[i][j][k] = 0.f;

    const int lrow = tid >> 2;
    const int lq   = tid & 3;

    auto load_stage = [&](int i, int s) {
        const int k0 = kbase + i * 32;
        const int ks = k0 >> 8;
        const int kc = (k0 & 255) + lq * 8;
        const int ky = ks >> 2, kx = ks & 3;
        const uint32_t st = sb + s * 20480;
#pragma unroll
        for (int e = 0; e < 2; e++) {
            int r = lrow + e * 64;
            int row = m0 + r;
            int bb = row >> 8, nkr = row & 255;
            int n = ((nkr >> 4) * 4 + ky) * HW + (nkr & 15) * 4 + kx;
            cpasync16(st +         r * 80 + lq * 16, Ah + ((size_t)bb * NN + n) * 256 + kc);
            cpasync16(st + 10240 + r * 80 + lq * 16, Bt + (size_t)(n0 + r) * K + k0 + lq * 8);
        }
        cpcommit();
    };

    auto compute_stage = [&](int s) {
        const uint32_t st = sb + s * 20480;
#pragma unroll
        for (int h = 0; h < 2; h++) {
            uint32_t a[4][4], bfr[4][2];
#pragma unroll
            for (int mt = 0; mt < 4; mt++) {
                int r = wm0 + mt * 16 + (lane & 15);
                ldm4(a[mt], st + r * 80 + h * 32 + (lane >> 4) * 16);
            }
#pragma unroll
            for (int ng = 0; ng < 2; ng++) {
                int r = wn0 + ng * 16 + (lane & 15);
                uint32_t t[4];
                ldm4(t, st + 10240 + r * 80 + h * 32 + (lane >> 4) * 16);
                bfr[2*ng][0] = t[0]; bfr[2*ng][1] = t[2];
                bfr[2*ng+1][0] = t[1]; bfr[2*ng+1][1] = t[3];
            }
#pragma unroll
            for (int mt = 0; mt < 4; mt++)
#pragma unroll
                for (int nt = 0; nt < 4; nt++)
                    mma16816h(c[mt][nt], a[mt], bfr[nt]);
        }
    };

    load_stage(0, 0);
    load_stage(1, 1);
    int stage = 0;
    for (int i = 0; i < nk; i++) {
        cpwait<1>();
        __syncthreads();
        if (i + 2 < nk) {
            int s2 = stage + 2; if (s2 >= 3) s2 -= 3;
            load_stage(i + 2, s2);
        }
        compute_stage(stage);
        if (++stage == 3) stage = 0;
    }

#pragma unroll
    for (int mt = 0; mt < 4; mt++)
#pragma unroll
        for (int nt = 0; nt < 4; nt++) {
            int row = m0 + wm0 + mt * 16 + (lane >> 2);
            int col = n0 + wn0 + nt * 8 + (lane & 3) * 2;
            *reinterpret_cast<float2*>(Cf + (size_t)row * N + col) =
                make_float2(c[mt][nt][0], c[mt][nt][1]);
            *reinterpret_cast<float2*>(Cf + (size_t)(row + 8) * N + col) =
                make_float2(c[mt][nt][2], c[mt][nt][3]);
        }
}

// ---------------- fused split-K reduce + bias + srn LayerNorm -> fp16 ----------------
__global__ void reduce_ln(const float* __restrict__ part, const float* __restrict__ cbias,
                          const float* __restrict__ w, const float* __restrict__ b,
                          __half* __restrict__ y, int MN, float eps)
{
    int row  = blockIdx.x * 8 + (threadIdx.x >> 5);
    int lane = threadIdx.x & 31;
    int c0 = lane * 8;
    float vals[8];
    {
        float4 b0 = *reinterpret_cast<const float4*>(cbias + c0);
        float4 b1 = *reinterpret_cast<const float4*>(cbias + c0 + 4);
        vals[0] = b0.x; vals[1] = b0.y; vals[2] = b0.z; vals[3] = b0.w;
        vals[4] = b1.x; vals[5] = b1.y; vals[6] = b1.z; vals[7] = b1.w;
    }
    for (int z = 0; z < 8; z++) {
        const float* p = part + (size_t)z * MN + (size_t)row * 256 + c0;
        float4 p0 = *reinterpret_cast<const float4*>(p);
        float4 p1 = *reinterpret_cast<const float4*>(p + 4);
        vals[0] += p0.x; vals[1] += p0.y; vals[2] += p0.z; vals[3] += p0.w;
        vals[4] += p1.x; vals[5] += p1.y; vals[6] += p1.z; vals[7] += p1.w;
    }
    float s = 0.f, sq = 0.f;
#pragma unroll
    for (int i = 0; i < 8; i++) { s += vals[i]; sq += vals[i] * vals[i]; }
#pragma unroll
    for (int o = 16; o > 0; o >>= 1) {
        s  += __shfl_xor_sync(0xffffffffu, s, o);
        sq += __shfl_xor_sync(0xffffffffu, sq, o);
    }
    float mean = s * (1.0f / 256.0f);
    float var  = sq * (1.0f / 256.0f) - mean * mean;
    float rs   = rsqrtf(var + eps);
    __align__(16) __half hb[8];
#pragma unroll
    for (int i = 0; i < 8; i++) {
        int c = c0 + i;
        hb[i] = __float2half_rn((vals[i] - mean) * rs * w[c] + b[c]);
    }
    *reinterpret_cast<uint4*>(y + (size_t)row * 256 + c0) = *reinterpret_cast<uint4*>(hb);
}

// ---------------- LayerNorm(256) -> fp16 ----------------
__global__ void ln256_h(const float* __restrict__ x, const float* __restrict__ w,
                        const float* __restrict__ b, __half* __restrict__ y,
                        int rows, float eps)
{
    int row  = blockIdx.x * 8 + (threadIdx.x >> 5);
    int lane = threadIdx.x & 31;
    if (row >= rows) return;
    const float* xr = x + (size_t)row * 256;
    float4 v0 = *reinterpret_cast<const float4*>(xr + lane * 8);
    float4 v1 = *reinterpret_cast<const float4*>(xr + lane * 8 + 4);
    float vals[8] = {v0.x, v0.y, v0.z, v0.w, v1.x, v1.y, v1.z, v1.w};
    float s = 0.f, sq = 0.f;
#pragma unroll
    for (int i = 0; i < 8; i++) { s += vals[i]; sq += vals[i] * vals[i]; }
#pragma unroll
    for (int o = 16; o > 0; o >>= 1) {
        s  += __shfl_xor_sync(0xffffffffu, s, o);
        sq += __shfl_xor_sync(0xffffffffu, sq, o);
    }
    float mean = s * (1.0f / 256.0f);
    float var  = sq * (1.0f / 256.0f) - mean * mean;
    float rs   = rsqrtf(var + eps);
    __align__(16) __half hb[8];
#pragma unroll
    for (int i = 0; i < 8; i++) {
        int c = lane * 8 + i;
        hb[i] = __float2half_rn((vals[i] - mean) * rs * w[c] + b[c]);
    }
    *reinterpret_cast<uint4*>(y + (size_t)row * 256 + lane * 8) = *reinterpret_cast<uint4*>(hb);
}

// ---------------- all weight prep in ONE kernel ----------------
#define PREP_TOTAL (65536 + 131072 + 65536 + 262144 + 262144 + 1048576)
__global__ void prep_all(const float* __restrict__ qw,  const float* __restrict__ kvw,
                         const float* __restrict__ pjw, const float* __restrict__ f1w,
                         const float* __restrict__ f2w, const float* __restrict__ srw,
                         __half* __restrict__ qT,  __half* __restrict__ kvT,
                         __half* __restrict__ pjT, __half* __restrict__ f1T,
                         __half* __restrict__ f2T, __half* __restrict__ wtT)
{
    int idx = blockIdx.x * 256 + threadIdx.x;
    if (idx < 65536) {
        int n = idx >> 8, k = idx & 255;
        qT[idx] = __float2half_rn(qw[k * 256 + n]);
        return;
    }
    idx -= 65536;
    if (idx < 131072) {
        int n = idx >> 8, k = idx & 255;
        kvT[idx] = __float2half_rn(kvw[k * 512 + n]);
        return;
    }
    idx -= 131072;
    if (idx < 65536) {
        int n = idx >> 8, k = idx & 255;
        pjT[idx] = __float2half_rn(pjw[k * 256 + n]);
        return;
    }
    idx -= 65536;
    if (idx < 262144) {
        int n = idx >> 8, k = idx & 255;
        f1T[idx] = __float2half_rn(f1w[k * 1024 + n]);
        return;
    }
    idx -= 262144;
    if (idx < 262144) {
        int n = idx >> 10, k = idx & 1023;
        f2T[idx] = __float2half_rn(f2w[k * 256 + n]);
        return;
    }
    idx -= 262144;
    {
        int co = idx >> 12, k = idx & 4095;
        int ks = k >> 8, ci = k & 255;
        wtT[idx] = __float2half_rn(srw[(size_t)co * KPATCH + ci * 16 + ks]);
    }
}

// ---------------- tensor-core attention, 64 q-row tiles, 2 CTAs/SM ----------------
#define AT_KT 0
#define AT_QT 20480
#define AT_VT 25600
#define AT_PM 42496
#define AT_PS 44544
#define POS_STRIDE 1040
#define ATTN_SMEM (44544 + 64 * POS_STRIDE)

__global__ __launch_bounds__(256, 2)
void attn_mma(const __half* __restrict__ qg, const __half* __restrict__ kvg,
              const float* __restrict__ pos, const float* __restrict__ alpha,
              __half* __restrict__ og)
{
    extern __shared__ char sm[];
    uint32_t sb = smem_u32(sm);
    const int tid = threadIdx.x, warp = tid >> 5, lane = tid & 31;
    const int n0 = blockIdx.x * 64, hh = blockIdx.y, b = blockIdx.z;

    // ---- K/V/Q loads FIRST (critical path for phase 1) ----
    {
        const __half* kb = kvg + ((size_t)b * NK) * 512 + hh * 32;
        for (int t = tid; t < 1024; t += 256) {
            int m = t >> 2, ch = t & 3;
            uint4 v = *reinterpret_cast<const uint4*>(kb + (size_t)m * 512 + ch * 8);
            *reinterpret_cast<uint4*>(sm + AT_KT + m * 80 + ch * 16) = v;
        }
        const __half* vb = kb + 256;
        for (int t = tid; t < 1024; t += 256) {
            int m = t >> 2, ch = t & 3;
            union { uint4 u; __half h[8]; } v;
            v.u = *reinterpret_cast<const uint4*>(vb + (size_t)m * 512 + ch * 8);
#pragma unroll
            for (int j = 0; j < 8; j++)
                *reinterpret_cast<__half*>(sm + AT_VT + (ch * 8 + j) * 528 + m * 2) = v.h[j];
        }
        const __half* qb = qg + ((size_t)b * NN + n0) * 256 + hh * 32;
        for (int t = tid; t < 256; t += 256) {
            int r = t >> 2, ch = t & 3;
            uint4 v = *reinterpret_cast<const uint4*>(qb + (size_t)r * 256 + ch * 8);
            *reinterpret_cast<uint4*>(sm + AT_QT + r * 80 + ch * 16) = v;
        }
    }

    // ---- pos tile prefetch (needed only at blend) — issued after critical loads ----
    {
        const float* posb = pos + ((size_t)(b * HH + hh) * NN + n0) * NK;
        for (int t = tid; t < 4096; t += 256) {
            int r = t >> 6, ch = t & 63;
            cpasync16(sb + AT_PS + r * POS_STRIDE + ch * 16, posb + (size_t)r * NK + ch * 4);
        }
        cpcommit();
    }
    __syncthreads();

    const int wm = (warp >> 2) * 32, wn = (warp & 3) * 64, slab = warp & 3;

    // ---- phase 1: S = Q @ K^T ----
    float c[2][8][4];
#pragma unroll
    for (int i = 0; i < 2; i++)
#pragma unroll
        for (int j = 0; j < 8; j++)
#pragma unroll
            for (int k = 0; k < 4; k++) c[i][j][k] = 0.f;

#pragma unroll
    for (int h = 0; h < 2; h++) {
        uint32_t a[2][4], bf[8][2];
#pragma unroll
        for (int mt = 0; mt < 2; mt++) {
            int r = wm + mt * 16 + (lane & 15);
            ldm4(a[mt], sb + AT_QT + r * 80 + h * 32 + (lane >> 4) * 16);
        }
#pragma unroll
        for (int ng = 0; ng < 4; ng++) {
            int r = wn + ng * 16 + (lane & 15);
            uint32_t t[4];
            ldm4(t, sb + AT_KT + r * 80 + h * 32 + (lane >> 4) * 16);
            bf[2*ng][0] = t[0]; bf[2*ng][1] = t[2];
            bf[2*ng+1][0] = t[1]; bf[2*ng+1][1] = t[3];
        }
#pragma unroll
        for (int mt = 0; mt < 2; mt++)
#pragma unroll
            for (int nt = 0; nt < 8; nt++)
                mma16816h(c[mt][nt], a[mt], bf[nt]);
    }

    // ---- phase 2: softmax on fragments ----
    const float scale = 0.17677669529663687f;
    float a_ = alpha[0];
    float* pmax = reinterpret_cast<float*>(sm + AT_PM);
    float* psum = pmax + 256;

#pragma unroll
    for (int mt = 0; mt < 2; mt++) {
        float m1 = -1e30f, m2 = -1e30f;
#pragma unroll
        for (int nt = 0; nt < 8; nt++) {
            m1 = fmaxf(m1, fmaxf(c[mt][nt][0], c[mt][nt][1]));
            m2 = fmaxf(m2, fmaxf(c[mt][nt][2], c[mt][nt][3]));
        }
        m1 = fmaxf(m1, __shfl_xor_sync(0xffffffffu, m1, 1));
        m1 = fmaxf(m1, __shfl_xor_sync(0xffffffffu, m1, 2));
        m2 = fmaxf(m2, __shfl_xor_sync(0xffffffffu, m2, 1));
        m2 = fmaxf(m2, __shfl_xor_sync(0xffffffffu, m2, 2));
        if ((lane & 3) == 0) {
            int r1 = wm + mt * 16 + (lane >> 2);
            pmax[r1 * 4 + slab] = m1;
            pmax[(r1 + 8) * 4 + slab] = m2;
        }
    }
    __syncthreads();

#pragma unroll
    for (int mt = 0; mt < 2; mt++) {
        int r1 = wm + mt * 16 + (lane >> 2);
        float g1 = fmaxf(fmaxf(pmax[r1*4], pmax[r1*4+1]), fmaxf(pmax[r1*4+2], pmax[r1*4+3]));
        int r2 = r1 + 8;
        float g2 = fmaxf(fmaxf(pmax[r2*4], pmax[r2*4+1]), fmaxf(pmax[r2*4+2], pmax[r2*4+3]));
        float s1 = 0.f, s2 = 0.f;
#pragma unroll
        for (int nt = 0; nt < 8; nt++) {
            c[mt][nt][0] = expf((c[mt][nt][0] - g1) * scale); s1 += c[mt][nt][0];
            c[mt][nt][1] = expf((c[mt][nt][1] - g1) * scale); s1 += c[mt][nt][1];
            c[mt][nt][2] = expf((c[mt][nt][2] - g2) * scale); s2 += c[mt][nt][2];
            c[mt][nt][3] = expf((c[mt][nt][3] - g2) * scale); s2 += c[mt][nt][3];
        }
        s1 += __shfl_xor_sync(0xffffffffu, s1, 1);
        s1 += __shfl_xor_sync(0xffffffffu, s1, 2);
        s2 += __shfl_xor_sync(0xffffffffu, s2, 1);
        s2 += __shfl_xor_sync(0xffffffffu, s2, 2);
        if ((lane & 3) == 0) {
            psum[r1 * 4 + slab] = s1;
            psum[r2 * 4 + slab] = s2;
        }
    }
    cpwait<0>();      // pos tile resident
    __syncthreads();

    // normalize + blend pos (from smem) + pack to A-fragments
    uint32_t af[2][4][4];
#pragma unroll
    for (int mt = 0; mt < 2; mt++) {
        int r1 = wm + mt * 16 + (lane >> 2);
        int r2 = r1 + 8;
        float s1 = psum[r1*4] + psum[r1*4+1] + psum[r1*4+2] + psum[r1*4+3];
        float s2 = psum[r2*4] + psum[r2*4+1] + psum[r2*4+2] + psum[r2*4+3];
        float i1 = (1.0f - a_) / s1, i2 = (1.0f - a_) / s2;
        const char* p1 = sm + AT_PS + r1 * POS_STRIDE + (wn + (lane & 3) * 2) * 4;
        const char* p2 = sm + AT_PS + r2 * POS_STRIDE + (wn + (lane & 3) * 2) * 4;
#pragma unroll
        for (int nt = 0; nt < 8; nt++) {
            float2 q1 = *reinterpret_cast<const float2*>(p1 + nt * 32);
            float2 q2 = *reinterpret_cast<const float2*>(p2 + nt * 32);
            c[mt][nt][0] = c[mt][nt][0] * i1 + a_ * q1.x;
            c[mt][nt][1] = c[mt][nt][1] * i1 + a_ * q1.y;
            c[mt][nt][2] = c[mt][nt][2] * i2 + a_ * q2.x;
            c[mt][nt][3] = c[mt][nt][3] * i2 + a_ * q2.y;
        }
#pragma unroll
        for (int j = 0; j < 4; j++) {
            af[mt][j][0] = packh2(c[mt][2*j][0],   c[mt][2*j][1]);
            af[mt][j][1] = packh2(c[mt][2*j][2],   c[mt][2*j][3]);
            af[mt][j][2] = packh2(c[mt][2*j+1][0], c[mt][2*j+1][1]);
            af[mt][j][3] = packh2(c[mt][2*j+1][2], c[mt][2*j+1][3]);
        }
    }
    __syncthreads();   // pos reads done; pos region reused as Opart

    // ---- phase 3: O_partial = P_slab @ V_slab ----
    float oc[2][4][4];
#pragma unroll
    for (int i = 0; i < 2; i++)
#pragma unroll
        for (int j = 0; j < 4; j++)
#pragma unroll
            for (int k = 0; k < 4; k++) oc[i][j][k] = 0.f;

#pragma unroll
    for (int ks = 0; ks < 4; ks++) {
        uint32_t bv[4][2];
#pragma unroll
        for (int ng = 0; ng < 2; ng++) {
            int d = ng * 16 + (lane & 15);
            uint32_t t[4];
            ldm4(t, sb + AT_VT + d * 528 + (wn + ks * 16) * 2 + (lane >> 4) * 16);
            bv[2*ng][0] = t[0]; bv[2*ng][1] = t[2];
            bv[2*ng+1][0] = t[1]; bv[2*ng+1][1] = t[3];
        }
#pragma unroll
        for (int mt = 0; mt < 2; mt++)
#pragma unroll
            for (int nt = 0; nt < 4; nt++)
                mma16816h(oc[mt][nt], af[mt][ks], bv[nt]);
    }

    float* Op = reinterpret_cast<float*>(sm + AT_PS);
#pragma unroll
    for (int mt = 0; mt < 2; mt++)
#pragma unroll
        for (int nt = 0; nt < 4; nt++) {
            int r1 = wm + mt * 16 + (lane >> 2);
            int d  = nt * 8 + (lane & 3) * 2;
            *reinterpret_cast<float2*>(Op + ((r1 * 4 + slab) * 32 + d)) =
                make_float2(oc[mt][nt][0], oc[mt][nt][1]);
            *reinterpret_cast<float2*>(Op + (((r1 + 8) * 4 + slab) * 32 + d)) =
                make_float2(oc[mt][nt][2], oc[mt][nt][3]);
        }
    __syncthreads();

    for (int t = tid; t < 2048; t += 256) {
        int r = t >> 5, d = t & 31;
        float s = Op[(r*4+0)*32+d] + Op[(r*4+1)*32+d] + Op[(r*4+2)*32+d] + Op[(r*4+3)*32+d];
        og[((size_t)b * NN + n0 + r) * 256 + hh * 32 + d] = __float2half_rn(s);
    }
}

// ---------------- depthwise 3x3 + exact GELU (weights staged in smem) ----------------
__global__ void dw_gelu(const __half* __restrict__ m, const float* __restrict__ w,
                        const float* __restrict__ bias, __half* __restrict__ mi)
{
    __shared__ float wsm[HID * 9];
    __shared__ float bsm[HID];
    int y = blockIdx.x;
    int b = blockIdx.y;
    for (int i = threadIdx.x; i < HID * 9; i += blockDim.x) wsm[i] = w[i];
    for (int i = threadIdx.x; i < HID; i += blockDim.x) bsm[i] = bias[i];
    __syncthreads();

    for (int idx = threadIdx.x; idx < HW * (HID / 4); idx += blockDim.x) {
        int x  = idx >> 8;
        int c4 = idx & 255;
        int c  = c4 * 4;
        float acc[4] = {bsm[c], bsm[c+1], bsm[c+2], bsm[c+3]};
#pragma unroll
        for (int dy = -1; dy <= 1; dy++) {
            int yy = y + dy;
            if (yy < 0 || yy >= HW) continue;
#pragma unroll
            for (int dx = -1; dx <= 1; dx++) {
                int xx = x + dx;
                if (xx < 0 || xx >= HW) continue;
                int tap = (dy + 1) * 3 + (dx + 1);
                const __half2* p = reinterpret_cast<const __half2*>(
                    m + ((size_t)b * NN + yy * HW + xx) * HID + c);
                float2 f01 = __half22float2(p[0]);
                float2 f23 = __half22float2(p[1]);
                acc[0] += f01.x * wsm[(c + 0) * 9 + tap];
                acc[1] += f01.y * wsm[(c + 1) * 9 + tap];
                acc[2] += f23.x * wsm[(c + 2) * 9 + tap];
                acc[3] += f23.y * wsm[(c + 3) * 9 + tap];
            }
        }
        float gv[4];
#pragma unroll
        for (int j = 0; j < 4; j++)
            gv[j] = 0.5f * acc[j] * (1.0f + erff(acc[j] * 0.70710678118654752f));
        __half2* op = reinterpret_cast<__half2*>(mi + ((size_t)b * NN + y * HW + x) * HID + c);
        op[0] = __floats2half2_rn(gv[0], gv[1]);
        op[1] = __floats2half2_rn(gv[2], gv[3]);
    }
}

// ---------------- launch ----------------
extern "C" void kernel_launch(void* const* d_in, const int* in_sizes, int n_in,
                              void* d_out, int out_size)
{
    const float* x      = (const float*)d_in[0];
    const float* pos2d  = (const float*)d_in[1];
    const float* ln1_w  = (const float*)d_in[2];
    const float* ln1_b  = (const float*)d_in[3];
    const float* q_w    = (const float*)d_in[4];
    const float* q_b    = (const float*)d_in[5];
    const float* kv_w   = (const float*)d_in[6];
    const float* kv_b   = (const float*)d_in[7];
    const float* sr_w   = (const float*)d_in[8];
    const float* sr_b   = (const float*)d_in[9];
    const float* srn_w  = (const float*)d_in[10];
    const float* srn_b  = (const float*)d_in[11];
    const float* alpha  = (const float*)d_in[12];
    const float* proj_w = (const float*)d_in[13];
    const float* proj_b = (const float*)d_in[14];
    const float* ln2_w  = (const float*)d_in[15];
    const float* ln2_b  = (const float*)d_in[16];
    const float* fc1_w  = (const float*)d_in[17];
    const float* fc1_b  = (const float*)d_in[18];
    const float* dw_w   = (const float*)d_in[19];
    const float* dw_b   = (const float*)d_in[20];
    const float* fc2_w  = (const float*)d_in[21];
    const float* fc2_b  = (const float*)d_in[22];
    float* out = (float*)d_out;

    __half *h_h, *wtT, *hs_h, *q_h, *kv_h, *o_h, *h2_h, *m_h, *mi_h;
    __half *qT, *kvT, *pjT, *f1T, *f2T;
    float *x1, *part;
    cudaGetSymbolAddress((void**)&h_h,  g_h_h);
    cudaGetSymbolAddress((void**)&wtT,  g_wtT);
    cudaGetSymbolAddress((void**)&hs_h, g_hs_h);
    cudaGetSymbolAddress((void**)&q_h,  g_q_h);
    cudaGetSymbolAddress((void**)&kv_h, g_kv_h);
    cudaGetSymbolAddress((void**)&o_h,  g_o_h);
    cudaGetSymbolAddress((void**)&x1,   g_x1);
    cudaGetSymbolAddress((void**)&h2_h, g_h2_h);
    cudaGetSymbolAddress((void**)&m_h,  g_m_h);
    cudaGetSymbolAddress((void**)&mi_h, g_mi_h);
    cudaGetSymbolAddress((void**)&part, g_part);
    cudaGetSymbolAddress((void**)&qT,   g_qT);
    cudaGetSymbolAddress((void**)&kvT,  g_kvT);
    cudaGetSymbolAddress((void**)&pjT,  g_pjT);
    cudaGetSymbolAddress((void**)&f1T,  g_f1T);
    cudaGetSymbolAddress((void**)&f2T,  g_f2T);

    static cudaStream_t s2 = nullptr;
    static cudaEvent_t evA = nullptr, evP = nullptr, evB = nullptr, evQ = nullptr;
    static bool cfg = false;
    if (!cfg) {
        cudaFuncSetAttribute(gemm_h,  cudaFuncAttributeMaxDynamicSharedMemorySize, GEMM_SMEM);
        cudaFuncSetAttribute(gemm_sr, cudaFuncAttributeMaxDynamicSharedMemorySize, GEMM_SMEM);
        cudaFuncSetAttribute(attn_mma, cudaFuncAttributeMaxDynamicSharedMemorySize, ATTN_SMEM);
        cudaStreamCreateWithFlags(&s2, cudaStreamNonBlocking);
        cudaEventCreateWithFlags(&evA, cudaEventDisableTiming);
        cudaEventCreateWithFlags(&evP, cudaEventDisableTiming);
        cudaEventCreateWithFlags(&evB, cudaEventDisableTiming);
        cudaEventCreateWithFlags(&evQ, cudaEventDisableTiming);
        cfg = true;
    }

    const int ROWS = BB * NN;        // 32768
    const int ROWS_SR = BB * NK;     // 2048

    // fork: prep_all runs on s2 concurrently with LN1
    cudaEventRecord(evA, 0);
    cudaStreamWaitEvent(s2, evA, 0);
    prep_all<<<PREP_TOTAL / 256, 256, 0, s2>>>(q_w, kv_w, proj_w, fc1_w, fc2_w, sr_w,
                                               qT, kvT, pjT, f1T, f2T, wtT);
    cudaEventRecord(evP, s2);

    // main: 1. h = LN1(x) -> fp16
    ln256_h<<<ROWS / 8, 256>>>(x, ln1_w, ln1_b, h_h, ROWS, 1e-6f);
    cudaEventRecord(evB, 0);

    // s2: q GEMM (needs h_h + qT) runs concurrently with the SR chain
    cudaStreamWaitEvent(s2, evB, 0);
    gemm_h<<<dim3(CC / 128, ROWS / 128), 256, GEMM_SMEM, s2>>>(h_h, qT, q_b, nullptr,
                                                               nullptr, q_h, ROWS, CC, CC, 1);
    cudaEventRecord(evQ, s2);

    // main waits for wtT/kvT (prep) before SR chain
    cudaStreamWaitEvent(0, evP, 0);
    // 2. SR GEMM with implicit patch gather (split-K=8)
    gemm_sr<<<dim3(CC / 128, ROWS_SR / 128, 8), 256, GEMM_SMEM>>>(h_h, wtT, part,
                                                                  ROWS_SR, CC, KPATCH, 8);
    // 3. fused reduce + bias + srn LN -> fp16
    reduce_ln<<<ROWS_SR / 8, 256>>>(part, sr_b, srn_w, srn_b, hs_h, ROWS_SR * CC, 1e-5f);
    // 4. kv = hs @ kv_w + kv_b (fp16 out)
    gemm_h<<<dim3((2 * CC) / 128, ROWS_SR / 128), 256, GEMM_SMEM>>>(hs_h, kvT, kv_b, nullptr,
                                                                    nullptr, kv_h, ROWS_SR, 2 * CC, CC, 1);
    // join: attention needs q_h from s2
    cudaStreamWaitEvent(0, evQ, 0);
    // 5. tensor-core attention (64-row tiles, pos prefetch) -> o fp16
    attn_mma<<<dim3(NN / 64, HH, BB), 256, ATTN_SMEM>>>(q_h, kv_h, pos2d, alpha, o_h);
    // 6. proj: x1 = x + o @ proj_w + proj_b
    gemm_h<<<dim3(CC / 128, ROWS / 128), 256, GEMM_SMEM>>>(o_h, pjT, proj_b, x,
                                                           x1, nullptr, ROWS, CC, CC, 1);
    // 7. h2 = LN2(x1) -> fp16
    ln256_h<<<ROWS / 8, 256>>>(x1, ln2_w, ln2_b, h2_h, ROWS, 1e-6f);
    // 8. fc1: m = h2 @ fc1_w + fc1_b (fp16 out)
    gemm_h<<<dim3(HID / 128, ROWS / 128), 256, GEMM_SMEM>>>(h2_h, f1T, fc1_b, nullptr,
                                                            nullptr, m_h, ROWS, HID, CC, 1);
    // 9. depthwise conv + gelu
    dw_gelu<<<dim3(HW, BB), 512>>>(m_h, dw_w, dw_b, mi_h);
    // 10. fc2: out = x1 + mi @ fc2_w + fc2_b
    gemm_h<<<dim3(CC / 128, ROWS / 128), 256, GEMM_SMEM>>>(mi_h, f2T, fc2_b, x1,
                                                           out, nullptr, ROWS, CC, HID, 1);
}

// round 17
// speedup vs baseline: 1.1488x; 1.0885x over previous
#include <cuda_runtime.h>
#include <cuda_fp16.h>
#include <math.h>
#include <stdint.h>

// Problem dims (fixed)
#define BB   8
#define NN   4096
#define CC   256
#define HH   8
#define DH   32
#define HW   64
#define NK   256
#define HID  1024
#define KPATCH 4096   // C * SR * SR

// ---------------- scratch (device globals; no allocation) ----------------
__device__ __half g_h_h [(size_t)BB*NN*CC];
__device__ __half g_wtT [(size_t)CC*KPATCH];
__device__ __half g_hs_h[(size_t)BB*NK*CC];
__device__ __half g_q_h [(size_t)BB*NN*CC];
__device__ __half g_kv_h[(size_t)BB*NK*2*CC];
__device__ __half g_o_h [(size_t)BB*NN*CC];
__device__ float  g_x1  [(size_t)BB*NN*CC];
__device__ __half g_h2_h[(size_t)BB*NN*CC];
__device__ __half g_m_h [(size_t)BB*NN*HID];
__device__ __half g_mi_h[(size_t)BB*NN*HID];
__device__ float  g_part[(size_t)8*BB*NK*CC];   // split-K partials
// transposed weights [N x K] fp16
__device__ __half g_qT [CC*CC];
__device__ __half g_kvT[2*CC*CC];
__device__ __half g_pjT[CC*CC];
__device__ __half g_f1T[HID*CC];
__device__ __half g_f2T[CC*HID];

// ---------------- PTX helpers (legal on base compute_103 target) ----------------
__device__ __forceinline__ uint32_t smem_u32(const void* p) {
    uint32_t a;
    asm("{ .reg .u64 t; cvta.to.shared.u64 t, %1; cvt.u32.u64 %0, t; }" : "=r"(a) : "l"(p));
    return a;
}
__device__ __forceinline__ void cpasync16(uint32_t dst, const void* src) {
    asm volatile("cp.async.cg.shared.global [%0], [%1], 16;" :: "r"(dst), "l"(src) : "memory");
}
__device__ __forceinline__ void cpcommit() {
    asm volatile("cp.async.commit_group;" ::: "memory");
}
template<int Ngrp> __device__ __forceinline__ void cpwait() {
    asm volatile("cp.async.wait_group %0;" :: "n"(Ngrp) : "memory");
}
__device__ __forceinline__ void ldm4(uint32_t* r, uint32_t addr) {
    asm volatile("ldmatrix.sync.aligned.m8n8.x4.shared.b16 {%0,%1,%2,%3}, [%4];"
                 : "=r"(r[0]), "=r"(r[1]), "=r"(r[2]), "=r"(r[3]) : "r"(addr));
}
__device__ __forceinline__ void mma16816h(float* c, const uint32_t* a, const uint32_t* b) {
    asm volatile("mma.sync.aligned.m16n8k16.row.col.f32.f16.f16.f32 "
                 "{%0,%1,%2,%3}, {%4,%5,%6,%7}, {%8,%9}, {%0,%1,%2,%3};"
                 : "+f"(c[0]), "+f"(c[1]), "+f"(c[2]), "+f"(c[3])
                 : "r"(a[0]), "r"(a[1]), "r"(a[2]), "r"(a[3]), "r"(b[0]), "r"(b[1]));
}
__device__ __forceinline__ uint32_t packh2(float x, float y) {
    __half2 h = __floats2half2_rn(x, y);
    return *reinterpret_cast<uint32_t*>(&h);
}

// ---------------- fp16 tensor GEMM via mma.sync, 3-stage pipeline ----------------
#define GEMM_SMEM (3 * 20480)

__global__ __launch_bounds__(256, 2)
void gemm_h(const __half* __restrict__ A, const __half* __restrict__ Bt,
            const float* __restrict__ bias, const float* __restrict__ res,
            float* __restrict__ Cf, __half* __restrict__ Ch,
            int M, int N, int K, int splitK)
{
    extern __shared__ char sm[];
    uint32_t sb = smem_u32(sm);
    const int tid  = threadIdx.x;
    const int warp = tid >> 5, lane = tid & 31;
    const int n0 = blockIdx.x * 128, m0 = blockIdx.y * 128;
    const int Keff  = K / splitK;
    const int kbase = blockIdx.z * Keff;
    if (splitK > 1) Cf += (size_t)blockIdx.z * M * N;
    const int nk = Keff / 32;
    const int wm0 = (warp >> 2) * 64, wn0 = (warp & 3) * 32;

    float c[4][4][4];
#pragma unroll
    for (int i = 0; i < 4; i++)
#pragma unroll
        for (int j = 0; j < 4; j++)
#pragma unroll
            for (int k = 0; k < 4; k++) c[i][j][k] = 0.f;

    const int lrow = tid >> 2;
    const int lq   = tid & 3;

    auto load_stage = [&](int i, int s) {
        const int k0 = kbase + i * 32;
        const uint32_t st = sb + s * 20480;
#pragma unroll
        for (int e = 0; e < 2; e++) {
            int r = lrow + e * 64;
            cpasync16(st +         r * 80 + lq * 16, A  + (size_t)(m0 + r) * K + k0 + lq * 8);
            cpasync16(st + 10240 + r * 80 + lq * 16, Bt + (size_t)(n0 + r) * K + k0 + lq * 8);
        }
        cpcommit();
    };

    auto compute_stage = [&](int s) {
        const uint32_t st = sb + s * 20480;
#pragma unroll
        for (int h = 0; h < 2; h++) {
            uint32_t a[4][4], bfr[4][2];
#pragma unroll
            for (int mt = 0; mt < 4; mt++) {
                int r = wm0 + mt * 16 + (lane & 15);
                ldm4(a[mt], st + r * 80 + h * 32 + (lane >> 4) * 16);
            }
#pragma unroll
            for (int ng = 0; ng < 2; ng++) {
                int r = wn0 + ng * 16 + (lane & 15);
                uint32_t t[4];
                ldm4(t, st + 10240 + r * 80 + h * 32 + (lane >> 4) * 16);
                bfr[2*ng][0] = t[0]; bfr[2*ng][1] = t[2];
                bfr[2*ng+1][0] = t[1]; bfr[2*ng+1][1] = t[3];
            }
#pragma unroll
            for (int mt = 0; mt < 4; mt++)
#pragma unroll
                for (int nt = 0; nt < 4; nt++)
                    mma16816h(c[mt][nt], a[mt], bfr[nt]);
        }
    };

    load_stage(0, 0);
    load_stage(1, 1);
    int stage = 0;
    for (int i = 0; i < nk; i++) {
        cpwait<1>();
        __syncthreads();
        if (i + 2 < nk) {
            int s2 = stage + 2; if (s2 >= 3) s2 -= 3;
            load_stage(i + 2, s2);
        }
        compute_stage(stage);
        if (++stage == 3) stage = 0;
    }

#pragma unroll
    for (int mt = 0; mt < 4; mt++)
#pragma unroll
        for (int nt = 0; nt < 4; nt++) {
            int row = m0 + wm0 + mt * 16 + (lane >> 2);
            int col = n0 + wn0 + nt * 8 + (lane & 3) * 2;
            float v0 = c[mt][nt][0], v1 = c[mt][nt][1];
            float v2 = c[mt][nt][2], v3 = c[mt][nt][3];
            if (splitK == 1) {
                float b0 = bias[col], b1 = bias[col + 1];
                v0 += b0; v1 += b1; v2 += b0; v3 += b1;
                if (res) {
                    const float* r0 = res + (size_t)row * N + col;
                    const float* r1 = res + (size_t)(row + 8) * N + col;
                    v0 += r0[0]; v1 += r0[1]; v2 += r1[0]; v3 += r1[1];
                }
            }
            if (Ch) {
                *reinterpret_cast<__half2*>(Ch + (size_t)row * N + col)       = __floats2half2_rn(v0, v1);
                *reinterpret_cast<__half2*>(Ch + (size_t)(row + 8) * N + col) = __floats2half2_rn(v2, v3);
            } else {
                *reinterpret_cast<float2*>(Cf + (size_t)row * N + col)       = make_float2(v0, v1);
                *reinterpret_cast<float2*>(Cf + (size_t)(row + 8) * N + col) = make_float2(v2, v3);
            }
        }
}

// ---------------- SR GEMM with IMPLICIT patch gather ----------------
__global__ __launch_bounds__(256, 2)
void gemm_sr(const __half* __restrict__ Ah, const __half* __restrict__ Bt,
             float* __restrict__ Cf, int M, int N, int K, int splitK)
{
    extern __shared__ char sm[];
    uint32_t sb = smem_u32(sm);
    const int tid  = threadIdx.x;
    const int warp = tid >> 5, lane = tid & 31;
    const int n0 = blockIdx.x * 128, m0 = blockIdx.y * 128;
    const int Keff  = K / splitK;
    const int kbase = blockIdx.z * Keff;
    Cf += (size_t)blockIdx.z * M * N;
    const int nk = Keff / 32;
    const int wm0 = (warp >> 2) * 64, wn0 = (warp & 3) * 32;

    float c[4][4][4];
#pragma unroll
    for (int i = 0; i < 4; i++)
#pragma unroll
        for (int j = 0; j < 4; j++)
#pragma unroll
            for (int k = 0; k < 4; k++) c[i][j][k] = 0.f;

    const int lrow = tid >> 2;
    const int lq   = tid & 3;

    auto load_stage = [&](int i, int s) {
        const int k0 = kbase + i * 32;
        const int ks = k0 >> 8;
        const int kc = (k0 & 255) + lq * 8;
        const int ky = ks >> 2, kx = ks & 3;
        const uint32_t st = sb + s * 20480;
#pragma unroll
        for (int e = 0; e < 2; e++) {
            int r = lrow + e * 64;
            int row = m0 + r;
            int bb = row >> 8, nkr = row & 255;
            int n = ((nkr >> 4) * 4 + ky) * HW + (nkr & 15) * 4 + kx;
            cpasync16(st +         r * 80 + lq * 16, Ah + ((size_t)bb * NN + n) * 256 + kc);
            cpasync16(st + 10240 + r * 80 + lq * 16, Bt + (size_t)(n0 + r) * K + k0 + lq * 8);
        }
        cpcommit();
    };

    auto compute_stage = [&](int s) {
        const uint32_t st = sb + s * 20480;
#pragma unroll
        for (int h = 0; h < 2; h++) {
            uint32_t a[4][4], bfr[4][2];
#pragma unroll
            for (int mt = 0; mt < 4; mt++) {
                int r = wm0 + mt * 16 + (lane & 15);
                ldm4(a[mt], st + r * 80 + h * 32 + (lane >> 4) * 16);
            }
#pragma unroll
            for (int ng = 0; ng < 2; ng++) {
                int r = wn0 + ng * 16 + (lane & 15);
                uint32_t t[4];
                ldm4(t, st + 10240 + r * 80 + h * 32 + (lane >> 4) * 16);
                bfr[2*ng][0] = t[0]; bfr[2*ng][1] = t[2];
                bfr[2*ng+1][0] = t[1]; bfr[2*ng+1][1] = t[3];
            }
#pragma unroll
            for (int mt = 0; mt < 4; mt++)
#pragma unroll
                for (int nt = 0; nt < 4; nt++)
                    mma16816h(c[mt][nt], a[mt], bfr[nt]);
        }
    };

    load_stage(0, 0);
    load_stage(1, 1);
    int stage = 0;
    for (int i = 0; i < nk; i++) {
        cpwait<1>();
        __syncthreads();
        if (i + 2 < nk) {
            int s2 = stage + 2; if (s2 >= 3) s2 -= 3;
            load_stage(i + 2, s2);
        }
        compute_stage(stage);
        if (++stage == 3) stage = 0;
    }

#pragma unroll
    for (int mt = 0; mt < 4; mt++)
#pragma unroll
        for (int nt = 0; nt < 4; nt++) {
            int row = m0 + wm0 + mt * 16 + (lane >> 2);
            int col = n0 + wn0 + nt * 8 + (lane & 3) * 2;
            *reinterpret_cast<float2*>(Cf + (size_t)row * N + col) =
                make_float2(c[mt][nt][0], c[mt][nt][1]);
            *reinterpret_cast<float2*>(Cf + (size_t)(row + 8) * N + col) =
                make_float2(c[mt][nt][2], c[mt][nt][3]);
        }
}

// ---------------- fused split-K reduce + bias + srn LayerNorm -> fp16 ----------------
__global__ void reduce_ln(const float* __restrict__ part, const float* __restrict__ cbias,
                          const float* __restrict__ w, const float* __restrict__ b,
                          __half* __restrict__ y, int MN, float eps)
{
    int row  = blockIdx.x * 8 + (threadIdx.x >> 5);
    int lane = threadIdx.x & 31;
    int c0 = lane * 8;
    float vals[8];
    {
        float4 b0 = *reinterpret_cast<const float4*>(cbias + c0);
        float4 b1 = *reinterpret_cast<const float4*>(cbias + c0 + 4);
        vals[0] = b0.x; vals[1] = b0.y; vals[2] = b0.z; vals[3] = b0.w;
        vals[4] = b1.x; vals[5] = b1.y; vals[6] = b1.z; vals[7] = b1.w;
    }
    for (int z = 0; z < 8; z++) {
        const float* p = part + (size_t)z * MN + (size_t)row * 256 + c0;
        float4 p0 = *reinterpret_cast<const float4*>(p);
        float4 p1 = *reinterpret_cast<const float4*>(p + 4);
        vals[0] += p0.x; vals[1] += p0.y; vals[2] += p0.z; vals[3] += p0.w;
        vals[4] += p1.x; vals[5] += p1.y; vals[6] += p1.z; vals[7] += p1.w;
    }
    float s = 0.f, sq = 0.f;
#pragma unroll
    for (int i = 0; i < 8; i++) { s += vals[i]; sq += vals[i] * vals[i]; }
#pragma unroll
    for (int o = 16; o > 0; o >>= 1) {
        s  += __shfl_xor_sync(0xffffffffu, s, o);
        sq += __shfl_xor_sync(0xffffffffu, sq, o);
    }
    float mean = s * (1.0f / 256.0f);
    float var  = sq * (1.0f / 256.0f) - mean * mean;
    float rs   = rsqrtf(var + eps);
    __align__(16) __half hb[8];
#pragma unroll
    for (int i = 0; i < 8; i++) {
        int c = c0 + i;
        hb[i] = __float2half_rn((vals[i] - mean) * rs * w[c] + b[c]);
    }
    *reinterpret_cast<uint4*>(y + (size_t)row * 256 + c0) = *reinterpret_cast<uint4*>(hb);
}

// ---------------- LayerNorm(256) -> fp16 ----------------
__global__ void ln256_h(const float* __restrict__ x, const float* __restrict__ w,
                        const float* __restrict__ b, __half* __restrict__ y,
                        int rows, float eps)
{
    int row  = blockIdx.x * 8 + (threadIdx.x >> 5);
    int lane = threadIdx.x & 31;
    if (row >= rows) return;
    const float* xr = x + (size_t)row * 256;
    float4 v0 = *reinterpret_cast<const float4*>(xr + lane * 8);
    float4 v1 = *reinterpret_cast<const float4*>(xr + lane * 8 + 4);
    float vals[8] = {v0.x, v0.y, v0.z, v0.w, v1.x, v1.y, v1.z, v1.w};
    float s = 0.f, sq = 0.f;
#pragma unroll
    for (int i = 0; i < 8; i++) { s += vals[i]; sq += vals[i] * vals[i]; }
#pragma unroll
    for (int o = 16; o > 0; o >>= 1) {
        s  += __shfl_xor_sync(0xffffffffu, s, o);
        sq += __shfl_xor_sync(0xffffffffu, sq, o);
    }
    float mean = s * (1.0f / 256.0f);
    float var  = sq * (1.0f / 256.0f) - mean * mean;
    float rs   = rsqrtf(var + eps);
    __align__(16) __half hb[8];
#pragma unroll
    for (int i = 0; i < 8; i++) {
        int c = lane * 8 + i;
        hb[i] = __float2half_rn((vals[i] - mean) * rs * w[c] + b[c]);
    }
    *reinterpret_cast<uint4*>(y + (size_t)row * 256 + lane * 8) = *reinterpret_cast<uint4*>(hb);
}

// ---------------- all weight prep in ONE kernel ----------------
#define PREP_TOTAL (65536 + 131072 + 65536 + 262144 + 262144 + 1048576)
__global__ void prep_all(const float* __restrict__ qw,  const float* __restrict__ kvw,
                         const float* __restrict__ pjw, const float* __restrict__ f1w,
                         const float* __restrict__ f2w, const float* __restrict__ srw,
                         __half* __restrict__ qT,  __half* __restrict__ kvT,
                         __half* __restrict__ pjT, __half* __restrict__ f1T,
                         __half* __restrict__ f2T, __half* __restrict__ wtT)
{
    int idx = blockIdx.x * 256 + threadIdx.x;
    if (idx < 65536) {
        int n = idx >> 8, k = idx & 255;
        qT[idx] = __float2half_rn(qw[k * 256 + n]);
        return;
    }
    idx -= 65536;
    if (idx < 131072) {
        int n = idx >> 8, k = idx & 255;
        kvT[idx] = __float2half_rn(kvw[k * 512 + n]);
        return;
    }
    idx -= 131072;
    if (idx < 65536) {
        int n = idx >> 8, k = idx & 255;
        pjT[idx] = __float2half_rn(pjw[k * 256 + n]);
        return;
    }
    idx -= 65536;
    if (idx < 262144) {
        int n = idx >> 8, k = idx & 255;
        f1T[idx] = __float2half_rn(f1w[k * 1024 + n]);
        return;
    }
    idx -= 262144;
    if (idx < 262144) {
        int n = idx >> 10, k = idx & 1023;
        f2T[idx] = __float2half_rn(f2w[k * 256 + n]);
        return;
    }
    idx -= 262144;
    {
        int co = idx >> 12, k = idx & 4095;
        int ks = k >> 8, ci = k & 255;
        wtT[idx] = __float2half_rn(srw[(size_t)co * KPATCH + ci * 16 + ks]);
    }
}

// ---------------- tensor-core attention, 64 q-row tiles, 2 CTAs/SM ----------------
// softmax WITHOUT max-subtraction (scores are tiny; exp(s*scale) is safe in fp32)
#define AT_KT 0
#define AT_QT 20480
#define AT_VT 25600
#define AT_PM 42496
#define AT_PS 44544
#define POS_STRIDE 1040
#define ATTN_SMEM (44544 + 64 * POS_STRIDE)

__global__ __launch_bounds__(256, 2)
void attn_mma(const __half* __restrict__ qg, const __half* __restrict__ kvg,
              const float* __restrict__ pos, const float* __restrict__ alpha,
              __half* __restrict__ og)
{
    extern __shared__ char sm[];
    uint32_t sb = smem_u32(sm);
    const int tid = threadIdx.x, warp = tid >> 5, lane = tid & 31;
    const int n0 = blockIdx.x * 64, hh = blockIdx.y, b = blockIdx.z;

    // ---- K/V/Q loads FIRST (critical path for phase 1) ----
    {
        const __half* kb = kvg + ((size_t)b * NK) * 512 + hh * 32;
        for (int t = tid; t < 1024; t += 256) {
            int m = t >> 2, ch = t & 3;
            uint4 v = *reinterpret_cast<const uint4*>(kb + (size_t)m * 512 + ch * 8);
            *reinterpret_cast<uint4*>(sm + AT_KT + m * 80 + ch * 16) = v;
        }
        const __half* vb = kb + 256;
        for (int t = tid; t < 1024; t += 256) {
            int m = t >> 2, ch = t & 3;
            union { uint4 u; __half h[8]; } v;
            v.u = *reinterpret_cast<const uint4*>(vb + (size_t)m * 512 + ch * 8);
#pragma unroll
            for (int j = 0; j < 8; j++)
                *reinterpret_cast<__half*>(sm + AT_VT + (ch * 8 + j) * 528 + m * 2) = v.h[j];
        }
        const __half* qb = qg + ((size_t)b * NN + n0) * 256 + hh * 32;
        for (int t = tid; t < 256; t += 256) {
            int r = t >> 2, ch = t & 3;
            uint4 v = *reinterpret_cast<const uint4*>(qb + (size_t)r * 256 + ch * 8);
            *reinterpret_cast<uint4*>(sm + AT_QT + r * 80 + ch * 16) = v;
        }
    }

    // ---- pos tile prefetch (needed only at blend) — issued after critical loads ----
    {
        const float* posb = pos + ((size_t)(b * HH + hh) * NN + n0) * NK;
        for (int t = tid; t < 4096; t += 256) {
            int r = t >> 6, ch = t & 63;
            cpasync16(sb + AT_PS + r * POS_STRIDE + ch * 16, posb + (size_t)r * NK + ch * 4);
        }
        cpcommit();
    }
    __syncthreads();

    const int wm = (warp >> 2) * 32, wn = (warp & 3) * 64, slab = warp & 3;

    // ---- phase 1: S = Q @ K^T ----
    float c[2][8][4];
#pragma unroll
    for (int i = 0; i < 2; i++)
#pragma unroll
        for (int j = 0; j < 8; j++)
#pragma unroll
            for (int k = 0; k < 4; k++) c[i][j][k] = 0.f;

#pragma unroll
    for (int h = 0; h < 2; h++) {
        uint32_t a[2][4], bf[8][2];
#pragma unroll
        for (int mt = 0; mt < 2; mt++) {
            int r = wm + mt * 16 + (lane & 15);
            ldm4(a[mt], sb + AT_QT + r * 80 + h * 32 + (lane >> 4) * 16);
        }
#pragma unroll
        for (int ng = 0; ng < 4; ng++) {
            int r = wn + ng * 16 + (lane & 15);
            uint32_t t[4];
            ldm4(t, sb + AT_KT + r * 80 + h * 32 + (lane >> 4) * 16);
            bf[2*ng][0] = t[0]; bf[2*ng][1] = t[2];
            bf[2*ng+1][0] = t[1]; bf[2*ng+1][1] = t[3];
        }
#pragma unroll
        for (int mt = 0; mt < 2; mt++)
#pragma unroll
            for (int nt = 0; nt < 8; nt++)
                mma16816h(c[mt][nt], a[mt], bf[nt]);
    }

    // ---- phase 2: softmax (no max subtraction) ----
    const float scale = 0.17677669529663687f;
    float a_ = alpha[0];
    float* psum = reinterpret_cast<float*>(sm + AT_PM);   // 256 floats

#pragma unroll
    for (int mt = 0; mt < 2; mt++) {
        int r1 = wm + mt * 16 + (lane >> 2);
        int r2 = r1 + 8;
        float s1 = 0.f, s2 = 0.f;
#pragma unroll
        for (int nt = 0; nt < 8; nt++) {
            c[mt][nt][0] = expf(c[mt][nt][0] * scale); s1 += c[mt][nt][0];
            c[mt][nt][1] = expf(c[mt][nt][1] * scale); s1 += c[mt][nt][1];
            c[mt][nt][2] = expf(c[mt][nt][2] * scale); s2 += c[mt][nt][2];
            c[mt][nt][3] = expf(c[mt][nt][3] * scale); s2 += c[mt][nt][3];
        }
        s1 += __shfl_xor_sync(0xffffffffu, s1, 1);
        s1 += __shfl_xor_sync(0xffffffffu, s1, 2);
        s2 += __shfl_xor_sync(0xffffffffu, s2, 1);
        s2 += __shfl_xor_sync(0xffffffffu, s2, 2);
        if ((lane & 3) == 0) {
            psum[r1 * 4 + slab] = s1;
            psum[r2 * 4 + slab] = s2;
        }
    }
    cpwait<0>();      // pos tile resident
    __syncthreads();

    // normalize + blend pos (from smem) + pack to A-fragments
    uint32_t af[2][4][4];
#pragma unroll
    for (int mt = 0; mt < 2; mt++) {
        int r1 = wm + mt * 16 + (lane >> 2);
        int r2 = r1 + 8;
        float s1 = psum[r1*4] + psum[r1*4+1] + psum[r1*4+2] + psum[r1*4+3];
        float s2 = psum[r2*4] + psum[r2*4+1] + psum[r2*4+2] + psum[r2*4+3];
        float i1 = (1.0f - a_) / s1, i2 = (1.0f - a_) / s2;
        const char* p1 = sm + AT_PS + r1 * POS_STRIDE + (wn + (lane & 3) * 2) * 4;
        const char* p2 = sm + AT_PS + r2 * POS_STRIDE + (wn + (lane & 3) * 2) * 4;
#pragma unroll
        for (int nt = 0; nt < 8; nt++) {
            float2 q1 = *reinterpret_cast<const float2*>(p1 + nt * 32);
            float2 q2 = *reinterpret_cast<const float2*>(p2 + nt * 32);
            c[mt][nt][0] = c[mt][nt][0] * i1 + a_ * q1.x;
            c[mt][nt][1] = c[mt][nt][1] * i1 + a_ * q1.y;
            c[mt][nt][2] = c[mt][nt][2] * i2 + a_ * q2.x;
            c[mt][nt][3] = c[mt][nt][3] * i2 + a_ * q2.y;
        }
#pragma unroll
        for (int j = 0; j < 4; j++) {
            af[mt][j][0] = packh2(c[mt][2*j][0],   c[mt][2*j][1]);
            af[mt][j][1] = packh2(c[mt][2*j][2],   c[mt][2*j][3]);
            af[mt][j][2] = packh2(c[mt][2*j+1][0], c[mt][2*j+1][1]);
            af[mt][j][3] = packh2(c[mt][2*j+1][2], c[mt][2*j+1][3]);
        }
    }
    __syncthreads();   // pos reads done; pos region reused as Opart

    // ---- phase 3: O_partial = P_slab @ V_slab ----
    float oc[2][4][4];
#pragma unroll
    for (int i = 0; i < 2; i++)
#pragma unroll
        for (int j = 0; j < 4; j++)
#pragma unroll
            for (int k = 0; k < 4; k++) oc[i][j][k] = 0.f;

#pragma unroll
    for (int ks = 0; ks < 4; ks++) {
        uint32_t bv[4][2];
#pragma unroll
        for (int ng = 0; ng < 2; ng++) {
            int d = ng * 16 + (lane & 15);
            uint32_t t[4];
            ldm4(t, sb + AT_VT + d * 528 + (wn + ks * 16) * 2 + (lane >> 4) * 16);
            bv[2*ng][0] = t[0]; bv[2*ng][1] = t[2];
            bv[2*ng+1][0] = t[1]; bv[2*ng+1][1] = t[3];
        }
#pragma unroll
        for (int mt = 0; mt < 2; mt++)
#pragma unroll
            for (int nt = 0; nt < 4; nt++)
                mma16816h(oc[mt][nt], af[mt][ks], bv[nt]);
    }

    float* Op = reinterpret_cast<float*>(sm + AT_PS);
#pragma unroll
    for (int mt = 0; mt < 2; mt++)
#pragma unroll
        for (int nt = 0; nt < 4; nt++) {
            int r1 = wm + mt * 16 + (lane >> 2);
            int d  = nt * 8 + (lane & 3) * 2;
            *reinterpret_cast<float2*>(Op + ((r1 * 4 + slab) * 32 + d)) =
                make_float2(oc[mt][nt][0], oc[mt][nt][1]);
            *reinterpret_cast<float2*>(Op + (((r1 + 8) * 4 + slab) * 32 + d)) =
                make_float2(oc[mt][nt][2], oc[mt][nt][3]);
        }
    __syncthreads();

    for (int t = tid; t < 2048; t += 256) {
        int r = t >> 5, d = t & 31;
        float s = Op[(r*4+0)*32+d] + Op[(r*4+1)*32+d] + Op[(r*4+2)*32+d] + Op[(r*4+3)*32+d];
        og[((size_t)b * NN + n0 + r) * 256 + hh * 32 + d] = __float2half_rn(s);
    }
}

// ---------------- depthwise 3x3 + exact GELU, smem-tiled ----------------
// grid (HW, 4 c-chunks of 256, BB), 256 threads, 2 CTAs/SM.
// smem: rows[3][64][256] fp16 (98304) | wsm 256*9 f32 (9216) | bsm 256 f32 (1024)
#define DW_ROWS 0
#define DW_W    98304
#define DW_B    (98304 + 9216)
#define DW_SMEM (98304 + 9216 + 1024)

__global__ __launch_bounds__(256, 2)
void dw_gelu(const __half* __restrict__ m, const float* __restrict__ w,
             const float* __restrict__ bias, __half* __restrict__ mi)
{
    extern __shared__ char sm[];
    __half* rows = reinterpret_cast<__half*>(sm + DW_ROWS);
    float* wsm = reinterpret_cast<float*>(sm + DW_W);
    float* bsm = reinterpret_cast<float*>(sm + DW_B);
    const int y  = blockIdx.x;
    const int c0 = blockIdx.y * 256;
    const int b  = blockIdx.z;
    const int tid = threadIdx.x;

    for (int i = tid; i < 256 * 9; i += 256) {
        int ci = i / 9, tap = i - ci * 9;
        wsm[ci * 9 + tap] = w[(c0 + ci) * 9 + tap];
    }
    for (int i = tid; i < 256; i += 256) bsm[i] = bias[c0 + i];

    // load 3 rows (y-1, y, y+1) of [64 x][256 c] fp16; valid rows only
    const int ylo = (y > 0) ? y - 1 : y;
    const int yhi = (y < HW - 1) ? y + 1 : y;
    for (int r = ylo; r <= yhi; r++) {
        int slot = r - y + 1;
        const __half* src = m + ((size_t)b * NN + r * HW) * HID + c0;
        // 64 x * 256 c = 16384 halves = 2048 uint4
        for (int t = tid; t < 2048; t += 256) {
            int xx = t >> 5, ch = t & 31;          // 32 uint4 per x
            *reinterpret_cast<uint4*>(rows + (slot * 64 + xx) * 256 + ch * 8) =
                *reinterpret_cast<const uint4*>(src + (size_t)xx * HID + ch * 8);
        }
    }
    __syncthreads();

    // compute: (x, c2) pairs; 64*128 = 8192 units / 256 thr = 32 per thread
    for (int t = tid; t < 8192; t += 256) {
        int x  = t >> 7;
        int c2 = t & 127;
        int c  = c2 * 2;
        float a0 = bsm[c], a1 = bsm[c + 1];
#pragma unroll
        for (int dy = 0; dy < 3; dy++) {
            int yy = y + dy - 1;
            if (yy < 0 || yy >= HW) continue;
#pragma unroll
            for (int dx = -1; dx <= 1; dx++) {
                int xx = x + dx;
                if (xx < 0 || xx >= HW) continue;
                int tap = dy * 3 + (dx + 1);
                __half2 v = *reinterpret_cast<const __half2*>(rows + (dy * 64 + xx) * 256 + c);
                float2 f = __half22float2(v);
                a0 += f.x * wsm[c * 9 + tap];
                a1 += f.y * wsm[(c + 1) * 9 + tap];
            }
        }
        float g0 = 0.5f * a0 * (1.0f + erff(a0 * 0.70710678118654752f));
        float g1 = 0.5f * a1 * (1.0f + erff(a1 * 0.70710678118654752f));
        *reinterpret_cast<__half2*>(mi + ((size_t)b * NN + y * HW + x) * HID + c0 + c) =
            __floats2half2_rn(g0, g1);
    }
}

// ---------------- launch ----------------
extern "C" void kernel_launch(void* const* d_in, const int* in_sizes, int n_in,
                              void* d_out, int out_size)
{
    const float* x      = (const float*)d_in[0];
    const float* pos2d  = (const float*)d_in[1];
    const float* ln1_w  = (const float*)d_in[2];
    const float* ln1_b  = (const float*)d_in[3];
    const float* q_w    = (const float*)d_in[4];
    const float* q_b    = (const float*)d_in[5];
    const float* kv_w   = (const float*)d_in[6];
    const float* kv_b   = (const float*)d_in[7];
    const float* sr_w   = (const float*)d_in[8];
    const float* sr_b   = (const float*)d_in[9];
    const float* srn_w  = (const float*)d_in[10];
    const float* srn_b  = (const float*)d_in[11];
    const float* alpha  = (const float*)d_in[12];
    const float* proj_w = (const float*)d_in[13];
    const float* proj_b = (const float*)d_in[14];
    const float* ln2_w  = (const float*)d_in[15];
    const float* ln2_b  = (const float*)d_in[16];
    const float* fc1_w  = (const float*)d_in[17];
    const float* fc1_b  = (const float*)d_in[18];
    const float* dw_w   = (const float*)d_in[19];
    const float* dw_b   = (const float*)d_in[20];
    const float* fc2_w  = (const float*)d_in[21];
    const float* fc2_b  = (const float*)d_in[22];
    float* out = (float*)d_out;

    __half *h_h, *wtT, *hs_h, *q_h, *kv_h, *o_h, *h2_h, *m_h, *mi_h;
    __half *qT, *kvT, *pjT, *f1T, *f2T;
    float *x1, *part;
    cudaGetSymbolAddress((void**)&h_h,  g_h_h);
    cudaGetSymbolAddress((void**)&wtT,  g_wtT);
    cudaGetSymbolAddress((void**)&hs_h, g_hs_h);
    cudaGetSymbolAddress((void**)&q_h,  g_q_h);
    cudaGetSymbolAddress((void**)&kv_h, g_kv_h);
    cudaGetSymbolAddress((void**)&o_h,  g_o_h);
    cudaGetSymbolAddress((void**)&x1,   g_x1);
    cudaGetSymbolAddress((void**)&h2_h, g_h2_h);
    cudaGetSymbolAddress((void**)&m_h,  g_m_h);
    cudaGetSymbolAddress((void**)&mi_h, g_mi_h);
    cudaGetSymbolAddress((void**)&part, g_part);
    cudaGetSymbolAddress((void**)&qT,   g_qT);
    cudaGetSymbolAddress((void**)&kvT,  g_kvT);
    cudaGetSymbolAddress((void**)&pjT,  g_pjT);
    cudaGetSymbolAddress((void**)&f1T,  g_f1T);
    cudaGetSymbolAddress((void**)&f2T,  g_f2T);

    static cudaStream_t s2 = nullptr;
    static cudaEvent_t evA = nullptr, evP = nullptr, evB = nullptr, evQ = nullptr;
    static bool cfg = false;
    if (!cfg) {
        cudaFuncSetAttribute(gemm_h,  cudaFuncAttributeMaxDynamicSharedMemorySize, GEMM_SMEM);
        cudaFuncSetAttribute(gemm_sr, cudaFuncAttributeMaxDynamicSharedMemorySize, GEMM_SMEM);
        cudaFuncSetAttribute(attn_mma, cudaFuncAttributeMaxDynamicSharedMemorySize, ATTN_SMEM);
        cudaFuncSetAttribute(dw_gelu, cudaFuncAttributeMaxDynamicSharedMemorySize, DW_SMEM);
        cudaStreamCreateWithFlags(&s2, cudaStreamNonBlocking);
        cudaEventCreateWithFlags(&evA, cudaEventDisableTiming);
        cudaEventCreateWithFlags(&evP, cudaEventDisableTiming);
        cudaEventCreateWithFlags(&evB, cudaEventDisableTiming);
        cudaEventCreateWithFlags(&evQ, cudaEventDisableTiming);
        cfg = true;
    }

    const int ROWS = BB * NN;        // 32768
    const int ROWS_SR = BB * NK;     // 2048

    // fork: prep_all runs on s2 concurrently with LN1
    cudaEventRecord(evA, 0);
    cudaStreamWaitEvent(s2, evA, 0);
    prep_all<<<PREP_TOTAL / 256, 256, 0, s2>>>(q_w, kv_w, proj_w, fc1_w, fc2_w, sr_w,
                                               qT, kvT, pjT, f1T, f2T, wtT);
    cudaEventRecord(evP, s2);

    // main: 1. h = LN1(x) -> fp16
    ln256_h<<<ROWS / 8, 256>>>(x, ln1_w, ln1_b, h_h, ROWS, 1e-6f);
    cudaEventRecord(evB, 0);

    // s2: q GEMM (needs h_h + qT) runs concurrently with the SR chain
    cudaStreamWaitEvent(s2, evB, 0);
    gemm_h<<<dim3(CC / 128, ROWS / 128), 256, GEMM_SMEM, s2>>>(h_h, qT, q_b, nullptr,
                                                               nullptr, q_h, ROWS, CC, CC, 1);
    cudaEventRecord(evQ, s2);

    // main waits for wtT/kvT (prep) before SR chain
    cudaStreamWaitEvent(0, evP, 0);
    // 2. SR GEMM with implicit patch gather (split-K=8)
    gemm_sr<<<dim3(CC / 128, ROWS_SR / 128, 8), 256, GEMM_SMEM>>>(h_h, wtT, part,
                                                                  ROWS_SR, CC, KPATCH, 8);
    // 3. fused reduce + bias + srn LN -> fp16
    reduce_ln<<<ROWS_SR / 8, 256>>>(part, sr_b, srn_w, srn_b, hs_h, ROWS_SR * CC, 1e-5f);
    // 4. kv = hs @ kv_w + kv_b (fp16 out)
    gemm_h<<<dim3((2 * CC) / 128, ROWS_SR / 128), 256, GEMM_SMEM>>>(hs_h, kvT, kv_b, nullptr,
                                                                    nullptr, kv_h, ROWS_SR, 2 * CC, CC, 1);
    // join: attention needs q_h from s2
    cudaStreamWaitEvent(0, evQ, 0);
    // 5. tensor-core attention (no-max softmax) -> o fp16
    attn_mma<<<dim3(NN / 64, HH, BB), 256, ATTN_SMEM>>>(q_h, kv_h, pos2d, alpha, o_h);
    // 6. proj: x1 = x + o @ proj_w + proj_b
    gemm_h<<<dim3(CC / 128, ROWS / 128), 256, GEMM_SMEM>>>(o_h, pjT, proj_b, x,
                                                           x1, nullptr, ROWS, CC, CC, 1);
    // 7. h2 = LN2(x1) -> fp16
    ln256_h<<<ROWS / 8, 256>>>(x1, ln2_w, ln2_b, h2_h, ROWS, 1e-6f);
    // 8. fc1: m = h2 @ fc1_w + fc1_b (fp16 out)
    gemm_h<<<dim3(HID / 128, ROWS / 128), 256, GEMM_SMEM>>>(h2_h, f1T, fc1_b, nullptr,
                                                            nullptr, m_h, ROWS, HID, CC, 1);
    // 9. depthwise conv + gelu (smem-tiled)
    dw_gelu<<<dim3(HW, 4, BB), 256, DW_SMEM>>>(m_h, dw_w, dw_b, mi_h);
    // 10. fc2: out = x1 + mi @ fc2_w + fc2_b
    gemm_h<<<dim3(CC / 128, ROWS / 128), 256, GEMM_SMEM>>>(mi_h, f2T, fc2_b, x1,
                                                           out, nullptr, ROWS, CC, HID, 1);
}